// round 13
// baseline (speedup 1.0000x reference)
#include <cuda_runtime.h>
#include <math.h>

#define Bn     32
#define Sn     32
#define BS     1024
#define EMBn   300
#define HIDn   128
#define G4n    512
#define AUDn   74
#define D1n    16
#define D2n    16
#define DIMn   256
#define UNITSn 128
#define CELLn  64

typedef unsigned long long u64;

// ---------------- scratch ----------------
__device__ __align__(16) float sc_X[BS * G4n];
__device__ __align__(16) float sc_h[BS * HIDn];
__device__ __align__(16) float sc_RI[BS * 2 * DIMn];
__device__ __align__(16) float sc_WT[2 * DIMn * 2 * UNITSn];  // 512 x 256
__device__ float sc_weight[BS];
__device__ float sc_n1[BS];
__device__ __align__(16) float sc_r1i1[BS * 32];              // [r1(16)|i1(16)]
__device__ __align__(16) float sc_PP4[4][BS * 2 * UNITSn];    // 4 K-split partials

// ---------------- f32x2 / ptx helpers ----------------
__device__ __forceinline__ u64 pk2(float x, float y) {
    u64 r; asm("mov.b64 %0,{%1,%2};" : "=l"(r) : "f"(x), "f"(y)); return r;
}
__device__ __forceinline__ void upk2(float& x, float& y, u64 v) {
    asm("mov.b64 {%0,%1},%2;" : "=f"(x), "=f"(y) : "l"(v));
}
__device__ __forceinline__ void fma2(u64& d, u64 a, u64 b) {
    asm("fma.rn.f32x2 %0,%1,%2,%0;" : "+l"(d) : "l"(a), "l"(b));
}
__device__ __forceinline__ float ex2f(float x) {
    float y; asm("ex2.approx.f32 %0,%1;" : "=f"(y) : "f"(x)); return y;
}
__device__ __forceinline__ float rcpf(float x) {
    float y; asm("rcp.approx.f32 %0,%1;" : "=f"(y) : "f"(x)); return y;
}
__device__ __forceinline__ float sigm_fast(float x) {
    return rcpf(1.0f + ex2f(-1.4426950408889634f * x));
}
__device__ __forceinline__ float tanh_fast(float x) {
    return 1.0f - 2.0f * rcpf(1.0f + ex2f(2.8853900817779268f * x));
}
__device__ __forceinline__ unsigned s2u(const void* p) {
    return (unsigned)__cvta_generic_to_shared(p);
}
__device__ __forceinline__ unsigned mapa32(unsigned a, unsigned r) {
    unsigned d; asm("mapa.shared::cluster.u32 %0,%1,%2;" : "=r"(d) : "r"(a), "r"(r));
    return d;
}
__device__ __forceinline__ void mbar_init(unsigned a, unsigned cnt) {
    asm volatile("mbarrier.init.shared.b64 [%0], %1;" :: "r"(a), "r"(cnt) : "memory");
}
__device__ __forceinline__ void mbar_arrive_remote(unsigned a) {
    asm volatile("mbarrier.arrive.release.cluster.shared::cluster.b64 _, [%0];"
                 :: "r"(a) : "memory");
}
__device__ __forceinline__ void st_remote_f32(unsigned a, float v) {
    asm volatile("st.shared::cluster.f32 [%0], %1;" :: "r"(a), "f"(v) : "memory");
}
__device__ __forceinline__ void mbar_waitc(unsigned a, unsigned parity) {
    asm volatile(
        "{\n\t.reg .pred P;\n"
        "WL%=:\n\t"
        "mbarrier.try_wait.parity.acquire.cluster.shared::cta.b64 P, [%0], %1;\n\t"
        "@P bra WD%=;\n\t"
        "bra WL%=;\n"
        "WD%=:\n\t}"
        :: "r"(a), "r"(parity) : "memory");
}

// ======= stage1: gemm_X (blk 0..127) | prep_WT (128..255) | audio (256..511) =======
__global__ void __launch_bounds__(128)
stage1(const int* __restrict__ word, const float* __restrict__ lut,
       const float* __restrict__ w_ih, const float* __restrict__ b_ih,
       const float* __restrict__ b_hh,
       const float* __restrict__ mr, const float* __restrict__ mi,
       const float* __restrict__ audio, const float* __restrict__ ph1t,
       const float* __restrict__ w1, const float* __restrict__ b1,
       const float* __restrict__ w2, const float* __restrict__ b2,
       const float* __restrict__ w3, const float* __restrict__ b3) {
    __shared__ float As[64 * 60];
    __shared__ float Bs[60 * 64];
    __shared__ int wd[64];
    __shared__ float red[4];
    __shared__ float sinv;
    const unsigned FULL = 0xffffffffu;
    int blk = blockIdx.x;
    int tid = threadIdx.x;

    if (blk < 128) {
        // ---------- gemm_X tile (identical to R12) ----------
        int j0 = (blk & 7) * 64, bs0 = (blk >> 3) * 64;
        int ct = tid & 7, rt = tid >> 3;
        if (tid < 64) wd[tid] = word[bs0 + tid];
        u64 acc[4][4];
#pragma unroll
        for (int q = 0; q < 4; q++)
#pragma unroll
            for (int p = 0; p < 4; p++) acc[q][p] = 0ull;
        int jb = j0 + ct * 8;
        float2 bi[4], bh[4];
#pragma unroll
        for (int p = 0; p < 4; p++) {
            bi[p] = *(const float2*)&b_ih[jb + 2 * p];
            bh[p] = *(const float2*)&b_hh[jb + 2 * p];
        }
        __syncthreads();
        for (int c = 0; c < 5; c++) {
            int kc = c * 60;
            for (int i = tid; i < 960; i += 128) {
                int r = i / 15, kq = i - r * 15;
                *(float4*)&As[r * 60 + kq * 4] =
                    *(const float4*)&lut[(long)wd[r] * EMBn + kc + kq * 4];
            }
            for (int i = tid; i < 960; i += 128) {
                int j = i / 15, kq = i - j * 15;
                float4 v = *(const float4*)&w_ih[(long)(j0 + j) * EMBn + kc + kq * 4];
                int kb = kq * 4;
                Bs[(kb + 0) * 64 + j] = v.x;
                Bs[(kb + 1) * 64 + j] = v.y;
                Bs[(kb + 2) * 64 + j] = v.z;
                Bs[(kb + 3) * 64 + j] = v.w;
            }
            __syncthreads();
#pragma unroll 5
            for (int kk = 0; kk < 60; kk += 4) {
                float4 a0 = *(const float4*)&As[(rt * 4 + 0) * 60 + kk];
                float4 a1 = *(const float4*)&As[(rt * 4 + 1) * 60 + kk];
                float4 a2 = *(const float4*)&As[(rt * 4 + 2) * 60 + kk];
                float4 a3 = *(const float4*)&As[(rt * 4 + 3) * 60 + kk];
#define XDOT(T, E0, E1, E2, E3) { \
                const u64* bp = (const u64*)&Bs[(kk + T) * 64 + ct * 8]; \
                u64 w0 = bp[0], w1v = bp[1], w2v = bp[2], w3v = bp[3]; \
                u64 e; \
                e = pk2(E0, E0); fma2(acc[0][0], e, w0); fma2(acc[0][1], e, w1v); fma2(acc[0][2], e, w2v); fma2(acc[0][3], e, w3v); \
                e = pk2(E1, E1); fma2(acc[1][0], e, w0); fma2(acc[1][1], e, w1v); fma2(acc[1][2], e, w2v); fma2(acc[1][3], e, w3v); \
                e = pk2(E2, E2); fma2(acc[2][0], e, w0); fma2(acc[2][1], e, w1v); fma2(acc[2][2], e, w2v); fma2(acc[2][3], e, w3v); \
                e = pk2(E3, E3); fma2(acc[3][0], e, w0); fma2(acc[3][1], e, w1v); fma2(acc[3][2], e, w2v); fma2(acc[3][3], e, w3v); }
                XDOT(0, a0.x, a1.x, a2.x, a3.x)
                XDOT(1, a0.y, a1.y, a2.y, a3.y)
                XDOT(2, a0.z, a1.z, a2.z, a3.z)
                XDOT(3, a0.w, a1.w, a2.w, a3.w)
#undef XDOT
            }
            __syncthreads();
        }
#pragma unroll
        for (int q = 0; q < 4; q++) {
            int row = bs0 + rt * 4 + q;
#pragma unroll
            for (int p = 0; p < 4; p++) {
                float lo, hi; upk2(lo, hi, acc[q][p]);
                *(float2*)&sc_X[row * G4n + jb + 2 * p] =
                    make_float2(lo + bi[p].x + bh[p].x, hi + bi[p].y + bh[p].y);
            }
        }
    } else if (blk < 256) {
        // ---------- prep_WT for unit u (128 threads, 2 d's each) ----------
        int u = blk - 128;
        float r0 = mr[u * DIMn + tid],       i0 = mi[u * DIMn + tid];
        float r1 = mr[u * DIMn + 128 + tid], i1 = mi[u * DIMn + 128 + tid];
        float s = r0 * r0 + i0 * i0 + r1 * r1 + i1 * i1;
#pragma unroll
        for (int sh = 16; sh; sh >>= 1) s += __shfl_xor_sync(FULL, s, sh);
        if ((tid & 31) == 0) red[tid >> 5] = s;
        __syncthreads();
        if (tid == 0)
            sinv = 1.0f / (sqrtf(red[0] + red[1] + red[2] + red[3]) + 1e-10f);
        __syncthreads();
        float inv = sinv;
        sc_WT[tid * 256 + u]                         = r0 * inv;
        sc_WT[tid * 256 + UNITSn + u]                = -i0 * inv;
        sc_WT[(DIMn + tid) * 256 + u]                = i0 * inv;
        sc_WT[(DIMn + tid) * 256 + UNITSn + u]       = r0 * inv;
        sc_WT[(tid + 128) * 256 + u]                 = r1 * inv;
        sc_WT[(tid + 128) * 256 + UNITSn + u]        = -i1 * inv;
        sc_WT[(DIMn + tid + 128) * 256 + u]          = i1 * inv;
        sc_WT[(DIMn + tid + 128) * 256 + UNITSn + u] = r1 * inv;
    } else {
        // ---------- audio branch, one warp per position ----------
        int lane = tid & 31;
        int bs = (blk - 256) * 4 + (tid >> 5);
        int o = lane & 15, half = lane >> 4;
        int w = word[bs];
        const float* ar = audio + bs * AUDn;
        const float* w1r = w1 + o * AUDn;
        float t = 0.f;
        int k0 = half * 37;
#pragma unroll
        for (int k = 0; k < 37; k++) t = fmaf(ar[k0 + k], w1r[k0 + k], t);
        t += __shfl_xor_sync(FULL, t, 16);
        float a1 = fmaxf(t + b1[o], 0.f);
        float s2 = b2[o];
#pragma unroll
        for (int k = 0; k < 16; k++)
            s2 = fmaf(__shfl_sync(FULL, a1, k), w2[o * 16 + k], s2);
        float a2 = fmaxf(s2, 0.f);
        float s3 = b3[o];
#pragma unroll
        for (int k = 0; k < 16; k++)
            s3 = fmaf(__shfl_sync(FULL, a2, k), w3[o * 16 + k], s3);
        float amp1 = fmaxf(s3, 0.f);
        float n1 = amp1 * amp1;
#pragma unroll
        for (int sh = 8; sh; sh >>= 1) n1 += __shfl_xor_sync(FULL, n1, sh);
        n1 = sqrtf(n1);
        if (lane == 0) sc_n1[bs] = n1;
        float an1 = amp1 / (n1 + 1e-10f);
        float p1 = ph1t[(long)w * D2n + o];
        float v = half ? (an1 * sinf(p1)) : (an1 * cosf(p1));
        sc_r1i1[bs * 32 + half * 16 + o] = v;
    }
}

// ---------------- K2: LSTM (regs weights, 2-CTA cluster/batch, fast act) ----------
__global__ void __launch_bounds__(256, 1) __cluster_dims__(2, 1, 1)
lstm_kernel(const float* __restrict__ w_hh) {
    __shared__ float Xs[Sn * 256];
    __shared__ __align__(16) float hbuf[2][HIDn];
    __shared__ float act[256];
    __shared__ __align__(8) u64 mbar[2];
    int tid = threadIdx.x;
    int b = blockIdx.x >> 1;
    unsigned rank = blockIdx.x & 1;
    unsigned peer = rank ^ 1;
    int q = tid >> 6, jj = tid & 63;
    int grow = q * 128 + (int)rank * 64 + jj;

    for (int t = 0; t < Sn; t++)
        Xs[t * 256 + tid] = sc_X[(b * Sn + t) * G4n + grow];
    if (tid < HIDn) hbuf[0][tid] = 0.f;
    unsigned mb0 = s2u(&mbar[0]);
    if (tid == 0) { mbar_init(mb0, 64); mbar_init(mb0 + 8, 64); }

    u64 w2r[64];
    const float4* wrow = (const float4*)(w_hh + (long)grow * HIDn);
#pragma unroll
    for (int k = 0; k < 32; k++) {
        float4 v = wrow[k];
        w2r[2 * k]     = pk2(v.x, v.y);
        w2r[2 * k + 1] = pk2(v.z, v.w);
    }
    __syncthreads();
    asm volatile("barrier.cluster.arrive.aligned;" ::: "memory");
    asm volatile("barrier.cluster.wait.aligned;" ::: "memory");

    unsigned peer_h  = mapa32(s2u(&hbuf[0][0]), peer);
    unsigned peer_mb = mapa32(mb0, peer);
    float c = 0.f;

    for (int t = 0; t < Sn; t++) {
        int cur = t & 1;
        if (t > 0) mbar_waitc(mb0 + cur * 8, ((unsigned)(t - 1) >> 1) & 1);
        const ulonglong2* hp = (const ulonglong2*)hbuf[cur];
        u64 a0 = 0ull, a1 = 0ull;
#pragma unroll
        for (int k = 0; k < 32; k++) {
            ulonglong2 hv = hp[k];
            fma2(a0, w2r[2 * k], hv.x);
            fma2(a1, w2r[2 * k + 1], hv.y);
        }
        float l0, h0, l1, h1;
        upk2(l0, h0, a0);
        upk2(l1, h1, a1);
        float g = Xs[t * 256 + tid] + ((l0 + h0) + (l1 + h1));
        act[tid] = (q == 2) ? tanh_fast(g) : sigm_fast(g);
        __syncthreads();
        if (tid < 64) {
            c = act[64 + tid] * c + act[tid] * act[128 + tid];
            float hh = act[192 + tid] * tanh_fast(c);
            int nxt = (t + 1) & 1;
            int hidx = (int)rank * 64 + tid;
            hbuf[nxt][hidx] = hh;
            sc_h[(b * Sn + t) * HIDn + hidx] = hh;
            if (t < Sn - 1) {
                st_remote_f32(peer_h + (unsigned)(nxt * HIDn + hidx) * 4u, hh);
                mbar_arrive_remote(peer_mb + (unsigned)nxt * 8u);
            }
        }
        __syncthreads();
    }
}

// ---------------- K3: combine_text — warp-per-position, audio precomputed -------
__global__ void __launch_bounds__(256, 4)
combine_text(const int* __restrict__ word,
             const float* __restrict__ ph0t,
             const float* __restrict__ w_lin, const float* __restrict__ b_lin,
             const float* __restrict__ modw) {
    const unsigned FULL = 0xffffffffu;
    int lane = threadIdx.x & 31;
    int bs = blockIdx.x * 8 + (threadIdx.x >> 5);
    int o = lane & 15, half = lane >> 4;
    int w = word[bs];

    const float* hp = sc_h + bs * HIDn + half * 64;
    const float* wl = w_lin + o * HIDn + half * 64;
    float s = 0.f;
#pragma unroll
    for (int k = 0; k < 64; k += 4) {
        float4 hv = *(const float4*)&hp[k];
        float4 wv = *(const float4*)&wl[k];
        s = fmaf(hv.x, wv.x, s); s = fmaf(hv.y, wv.y, s);
        s = fmaf(hv.z, wv.z, s); s = fmaf(hv.w, wv.w, s);
    }
    s += __shfl_xor_sync(FULL, s, 16);
    float amp0 = s + b_lin[o];

    float n0 = amp0 * amp0;
#pragma unroll
    for (int sh = 8; sh; sh >>= 1) n0 += __shfl_xor_sync(FULL, n0, sh);
    n0 = sqrtf(n0);
    float n1 = sc_n1[bs];

    if (lane == 0) {
        float e0 = expf(modw[0]), e1 = expf(modw[1]);
        sc_weight[bs] = (e0 * n0 + e1 * n1) / (e0 + e1);
    }

    float an0 = amp0 / (n0 + 1e-10f);
    float p0 = ph0t[(long)w * D1n + o];
    float rr = an0 * cosf(p0), ii = an0 * sinf(p0);
    float tpr = rr - ii, tpi = rr + ii;
    float r1l = sc_r1i1[bs * 32 + o];
    float i1l = sc_r1i1[bs * 32 + 16 + o];

    float* dst = sc_RI + bs * 2 * DIMn + half * DIMn;
#pragma unroll
    for (int i = 0; i < 16; i++) {
        float tr = __shfl_sync(FULL, tpr, i);
        float ti = __shfl_sync(FULL, tpi, i);
        float v = half ? fmaf(tr, i1l, ti * r1l) : (tr * r1l - ti * i1l);
        dst[i * 16 + o] = v;
    }
}

// ---- K4: (1024x512) @ WT(512x256), K-split 4, conflict-free B columns ----
__global__ void __launch_bounds__(128, 4)
gemm_M() {
    __shared__ float As[32 * 128];   // 16 KB
    __shared__ float Bs[128 * 64];   // 32 KB
    int tid = threadIdx.x;
    int j0 = blockIdx.x * 64, bs0 = blockIdx.y * 32;
    int kbase = blockIdx.z * 128;
    int ct = tid & 15, rt = tid >> 4;
#pragma unroll
    for (int i = tid; i < 1024; i += 128) {
        int r = i >> 5, kq = i & 31;
        *(float4*)&As[r * 128 + kq * 4] =
            *(const float4*)&sc_RI[(bs0 + r) * 512 + kbase + kq * 4];
    }
#pragma unroll
    for (int i = tid; i < 2048; i += 128) {
        int r = i >> 4, cq = i & 15;
        *(float4*)&Bs[r * 64 + cq * 4] =
            *(const float4*)&sc_WT[(kbase + r) * 256 + j0 + cq * 4];
    }
    u64 acc[4][2];
#pragma unroll
    for (int q = 0; q < 4; q++) { acc[q][0] = 0ull; acc[q][1] = 0ull; }
    __syncthreads();
#pragma unroll 4
    for (int kk = 0; kk < 128; kk += 4) {
        float4 a0 = *(const float4*)&As[(rt * 4 + 0) * 128 + kk];
        float4 a1 = *(const float4*)&As[(rt * 4 + 1) * 128 + kk];
        float4 a2 = *(const float4*)&As[(rt * 4 + 2) * 128 + kk];
        float4 a3 = *(const float4*)&As[(rt * 4 + 3) * 128 + kk];
#define MDOT(T, E0, E1, E2, E3) { \
        u64 w0 = *(const u64*)&Bs[(kk + T) * 64 + 2 * ct]; \
        u64 w1 = *(const u64*)&Bs[(kk + T) * 64 + 32 + 2 * ct]; \
        u64 e; \
        e = pk2(E0, E0); fma2(acc[0][0], e, w0); fma2(acc[0][1], e, w1); \
        e = pk2(E1, E1); fma2(acc[1][0], e, w0); fma2(acc[1][1], e, w1); \
        e = pk2(E2, E2); fma2(acc[2][0], e, w0); fma2(acc[2][1], e, w1); \
        e = pk2(E3, E3); fma2(acc[3][0], e, w0); fma2(acc[3][1], e, w1); }
        MDOT(0, a0.x, a1.x, a2.x, a3.x)
        MDOT(1, a0.y, a1.y, a2.y, a3.y)
        MDOT(2, a0.z, a1.z, a2.z, a3.z)
        MDOT(3, a0.w, a1.w, a2.w, a3.w)
#undef MDOT
    }
    float* dstbuf = sc_PP4[blockIdx.z];
#pragma unroll
    for (int q = 0; q < 4; q++) {
        int row = bs0 + rt * 4 + q;
        float lo, hi;
        upk2(lo, hi, acc[q][0]);
        *(float2*)&dstbuf[row * 256 + j0 + 2 * ct] = make_float2(lo, hi);
        upk2(lo, hi, acc[q][1]);
        *(float2*)&dstbuf[row * 256 + j0 + 32 + 2 * ct] = make_float2(lo, hi);
    }
}

// ---------------- K5: windows + max-pool + final MLP ----------------
__global__ void pool_mlp(const float* __restrict__ fw1, const float* __restrict__ fb1,
                         const float* __restrict__ fw2, const float* __restrict__ fb2,
                         const float* __restrict__ fw3, const float* __restrict__ fb3,
                         float* __restrict__ out) {
    __shared__ float Msm[Sn * UNITSn];
    __shared__ float esm[Sn + 2];
    __shared__ float feat[UNITSn], y1[CELLn], y2[CELLn], red[2];
    int b = blockIdx.x;
    int u = threadIdx.x;
    for (int s = 0; s < Sn; s++) {
        int base = (b * Sn + s) * 256;
        float pr = (sc_PP4[0][base + u] + sc_PP4[1][base + u])
                 + (sc_PP4[2][base + u] + sc_PP4[3][base + u]);
        float pi = (sc_PP4[0][base + 128 + u] + sc_PP4[1][base + 128 + u])
                 + (sc_PP4[2][base + 128 + u] + sc_PP4[3][base + 128 + u]);
        Msm[s * UNITSn + u] = pr * pr + pi * pi;
    }
    if (u < Sn) esm[u] = expf(sc_weight[b * Sn + u]);
    if (u >= Sn && u < Sn + 2) esm[u] = 1.0f;
    __syncthreads();
    float f = 0.f;
    for (int s = 0; s < Sn; s++) {
        float m0 = Msm[s * UNITSn + u];
        float m1 = (s + 1 < Sn) ? Msm[(s + 1) * UNITSn + u] : 0.f;
        float m2 = (s + 2 < Sn) ? Msm[(s + 2) * UNITSn + u] : 0.f;
        float e0 = esm[s], e1 = esm[s + 1], e2 = esm[s + 2];
        float p3 = (e0 * m0 + e1 * m1 + e2 * m2) / (e0 + e1 + e2);
        f = fmaxf(f, fmaxf(m0, p3));
    }
    feat[u] = f;
    __syncthreads();
    if (u < CELLn) {
        float s = fb1[u];
        for (int k = 0; k < UNITSn; k++) s = fmaf(feat[k], fw1[u * UNITSn + k], s);
        y1[u] = fmaxf(s, 0.f);
    }
    __syncthreads();
    if (u < CELLn) {
        float s = fb2[u];
        for (int k = 0; k < CELLn; k++) s = fmaf(y1[k], fw2[u * CELLn + k], s);
        y2[u] = fmaxf(s, 0.f);
    }
    __syncthreads();
    if (u < CELLn) {
        float v = y2[u] * fw3[u];
        for (int o = 16; o > 0; o >>= 1) v += __shfl_down_sync(0xffffffffu, v, o);
        if ((u & 31) == 0) red[u >> 5] = v;
    }
    __syncthreads();
    if (u == 0) out[b] = red[0] + red[1] + fb3[0];
}

// ---------------- launch ----------------
extern "C" void kernel_launch(void* const* d_in, const int* in_sizes, int n_in,
                              void* d_out, int out_size) {
    const int*   word  = (const int*)  d_in[0];
    const float* audio = (const float*)d_in[1];
    const float* lut   = (const float*)d_in[2];
    const float* ph0   = (const float*)d_in[3];
    const float* ph1   = (const float*)d_in[4];
    const float* w_ih  = (const float*)d_in[5];
    const float* w_hh  = (const float*)d_in[6];
    const float* b_ih  = (const float*)d_in[7];
    const float* b_hh  = (const float*)d_in[8];
    const float* w_lin = (const float*)d_in[9];
    const float* b_lin = (const float*)d_in[10];
    const float* w1    = (const float*)d_in[11];
    const float* b1    = (const float*)d_in[12];
    const float* w2    = (const float*)d_in[13];
    const float* b2    = (const float*)d_in[14];
    const float* w3    = (const float*)d_in[15];
    const float* b3    = (const float*)d_in[16];
    const float* modw  = (const float*)d_in[17];
    const float* mr    = (const float*)d_in[18];
    const float* mi    = (const float*)d_in[19];
    const float* fw1   = (const float*)d_in[20];
    const float* fb1   = (const float*)d_in[21];
    const float* fw2   = (const float*)d_in[22];
    const float* fb2   = (const float*)d_in[23];
    const float* fw3   = (const float*)d_in[24];
    const float* fb3   = (const float*)d_in[25];
    float* out = (float*)d_out;

    cudaFuncSetAttribute(gemm_M, cudaFuncAttributePreferredSharedMemoryCarveout, 100);

    stage1<<<512, 128>>>(word, lut, w_ih, b_ih, b_hh, mr, mi,
                         audio, ph1, w1, b1, w2, b2, w3, b3);
    lstm_kernel<<<64, 256>>>(w_hh);
    combine_text<<<128, 256>>>(word, ph0, w_lin, b_lin, modw);
    gemm_M<<<dim3(4, 32, 4), 128>>>();
    pool_mlp<<<32, 128>>>(fw1, fb1, fw2, fb2, fw3, fb3, out);
}

// round 14
// speedup vs baseline: 1.0993x; 1.0993x over previous
#include <cuda_runtime.h>
#include <math.h>

#define Bn     32
#define Sn     32
#define BS     1024
#define EMBn   300
#define HIDn   128
#define G4n    512
#define AUDn   74
#define D1n    16
#define D2n    16
#define DIMn   256
#define UNITSn 128
#define CELLn  64

typedef unsigned long long u64;

// ---------------- scratch ----------------
__device__ __align__(16) float sc_X[BS * G4n];
__device__ __align__(16) float sc_h[BS * HIDn];
__device__ __align__(16) float sc_RI[BS * 2 * DIMn];
__device__ __align__(16) float sc_WT[2 * DIMn * 2 * UNITSn];  // 512 x 256
__device__ float sc_weight[BS];
__device__ __align__(16) float sc_PP4[4][BS * 2 * UNITSn];    // 4 K-split partials

// ---------------- f32x2 / ptx helpers ----------------
__device__ __forceinline__ u64 pk2(float x, float y) {
    u64 r; asm("mov.b64 %0,{%1,%2};" : "=l"(r) : "f"(x), "f"(y)); return r;
}
__device__ __forceinline__ void upk2(float& x, float& y, u64 v) {
    asm("mov.b64 {%0,%1},%2;" : "=f"(x), "=f"(y) : "l"(v));
}
__device__ __forceinline__ void fma2(u64& d, u64 a, u64 b) {
    asm("fma.rn.f32x2 %0,%1,%2,%0;" : "+l"(d) : "l"(a), "l"(b));
}
__device__ __forceinline__ float ex2f(float x) {
    float y; asm("ex2.approx.f32 %0,%1;" : "=f"(y) : "f"(x)); return y;
}
__device__ __forceinline__ float rcpf(float x) {
    float y; asm("rcp.approx.f32 %0,%1;" : "=f"(y) : "f"(x)); return y;
}
__device__ __forceinline__ float sigm_fast(float x) {
    return rcpf(1.0f + ex2f(-1.4426950408889634f * x));
}
__device__ __forceinline__ float tanh_fast(float x) {
    return 1.0f - 2.0f * rcpf(1.0f + ex2f(2.8853900817779268f * x));
}
__device__ __forceinline__ unsigned s2u(const void* p) {
    return (unsigned)__cvta_generic_to_shared(p);
}
__device__ __forceinline__ unsigned mapa32(unsigned a, unsigned r) {
    unsigned d; asm("mapa.shared::cluster.u32 %0,%1,%2;" : "=r"(d) : "r"(a), "r"(r));
    return d;
}
__device__ __forceinline__ void mbar_init(unsigned a, unsigned cnt) {
    asm volatile("mbarrier.init.shared.b64 [%0], %1;" :: "r"(a), "r"(cnt) : "memory");
}
__device__ __forceinline__ void mbar_arrive_remote(unsigned a) {
    asm volatile("mbarrier.arrive.release.cluster.shared::cluster.b64 _, [%0];"
                 :: "r"(a) : "memory");
}
__device__ __forceinline__ void st_remote_f32(unsigned a, float v) {
    asm volatile("st.shared::cluster.f32 [%0], %1;" :: "r"(a), "f"(v) : "memory");
}
__device__ __forceinline__ void mbar_waitc(unsigned a, unsigned parity) {
    asm volatile(
        "{\n\t.reg .pred P;\n"
        "WL%=:\n\t"
        "mbarrier.try_wait.parity.acquire.cluster.shared::cta.b64 P, [%0], %1;\n\t"
        "@P bra WD%=;\n\t"
        "bra WL%=;\n"
        "WD%=:\n\t}"
        :: "r"(a), "r"(parity) : "memory");
}

// ---------------- K0: measurement matrix (norm + layout) ----------------
__global__ void prep_WT(const float* __restrict__ mr, const float* __restrict__ mi) {
    __shared__ float red[8];
    __shared__ float sinv;
    int u = blockIdx.x, tid = threadIdx.x;
    float r = mr[u * DIMn + tid], i = mi[u * DIMn + tid];
    float s = r * r + i * i;
    for (int sh = 16; sh; sh >>= 1) s += __shfl_down_sync(0xffffffffu, s, sh);
    if ((tid & 31) == 0) red[tid >> 5] = s;
    __syncthreads();
    if (tid == 0) {
        float t = 0.f;
        for (int k = 0; k < 8; k++) t += red[k];
        sinv = 1.0f / (sqrtf(t) + 1e-10f);
    }
    __syncthreads();
    float inv = sinv;
    sc_WT[tid * 256 + u]                   = r * inv;
    sc_WT[tid * 256 + UNITSn + u]          = -i * inv;
    sc_WT[(DIMn + tid) * 256 + u]          = i * inv;
    sc_WT[(DIMn + tid) * 256 + UNITSn + u] = r * inv;
}

// ---------------- K1: X = emb[word] @ w_ih.T + b_ih + b_hh ----------------
__global__ void gemm_X(const int* __restrict__ word,
                       const float* __restrict__ lut,
                       const float* __restrict__ w_ih,
                       const float* __restrict__ b_ih,
                       const float* __restrict__ b_hh) {
    __shared__ float As[64 * 60];
    __shared__ float Bs[60 * 64];
    __shared__ int wd[64];
    int tid = threadIdx.x;
    int j0 = blockIdx.x * 64, bs0 = blockIdx.y * 64;
    int ct = tid & 7, rt = tid >> 3;
    if (tid < 64) wd[tid] = word[bs0 + tid];
    u64 acc[4][4];
#pragma unroll
    for (int q = 0; q < 4; q++)
#pragma unroll
        for (int p = 0; p < 4; p++) acc[q][p] = 0ull;
    int jb = j0 + ct * 8;
    float2 bi[4], bh[4];
#pragma unroll
    for (int p = 0; p < 4; p++) {
        bi[p] = *(const float2*)&b_ih[jb + 2 * p];
        bh[p] = *(const float2*)&b_hh[jb + 2 * p];
    }
    __syncthreads();
    for (int c = 0; c < 5; c++) {
        int kc = c * 60;
        for (int i = tid; i < 960; i += 128) {
            int r = i / 15, kq = i - r * 15;
            *(float4*)&As[r * 60 + kq * 4] =
                *(const float4*)&lut[(long)wd[r] * EMBn + kc + kq * 4];
        }
        for (int i = tid; i < 960; i += 128) {
            int j = i / 15, kq = i - j * 15;
            float4 v = *(const float4*)&w_ih[(long)(j0 + j) * EMBn + kc + kq * 4];
            int kb = kq * 4;
            Bs[(kb + 0) * 64 + j] = v.x;
            Bs[(kb + 1) * 64 + j] = v.y;
            Bs[(kb + 2) * 64 + j] = v.z;
            Bs[(kb + 3) * 64 + j] = v.w;
        }
        __syncthreads();
#pragma unroll 5
        for (int kk = 0; kk < 60; kk += 4) {
            float4 a0 = *(const float4*)&As[(rt * 4 + 0) * 60 + kk];
            float4 a1 = *(const float4*)&As[(rt * 4 + 1) * 60 + kk];
            float4 a2 = *(const float4*)&As[(rt * 4 + 2) * 60 + kk];
            float4 a3 = *(const float4*)&As[(rt * 4 + 3) * 60 + kk];
#define XDOT(T, E0, E1, E2, E3) { \
            const u64* bp = (const u64*)&Bs[(kk + T) * 64 + ct * 8]; \
            u64 w0 = bp[0], w1v = bp[1], w2v = bp[2], w3v = bp[3]; \
            u64 e; \
            e = pk2(E0, E0); fma2(acc[0][0], e, w0); fma2(acc[0][1], e, w1v); fma2(acc[0][2], e, w2v); fma2(acc[0][3], e, w3v); \
            e = pk2(E1, E1); fma2(acc[1][0], e, w0); fma2(acc[1][1], e, w1v); fma2(acc[1][2], e, w2v); fma2(acc[1][3], e, w3v); \
            e = pk2(E2, E2); fma2(acc[2][0], e, w0); fma2(acc[2][1], e, w1v); fma2(acc[2][2], e, w2v); fma2(acc[2][3], e, w3v); \
            e = pk2(E3, E3); fma2(acc[3][0], e, w0); fma2(acc[3][1], e, w1v); fma2(acc[3][2], e, w2v); fma2(acc[3][3], e, w3v); }
            XDOT(0, a0.x, a1.x, a2.x, a3.x)
            XDOT(1, a0.y, a1.y, a2.y, a3.y)
            XDOT(2, a0.z, a1.z, a2.z, a3.z)
            XDOT(3, a0.w, a1.w, a2.w, a3.w)
#undef XDOT
        }
        __syncthreads();
    }
#pragma unroll
    for (int q = 0; q < 4; q++) {
        int row = bs0 + rt * 4 + q;
#pragma unroll
        for (int p = 0; p < 4; p++) {
            float lo, hi; upk2(lo, hi, acc[q][p]);
            *(float2*)&sc_X[row * G4n + jb + 2 * p] =
                make_float2(lo + bi[p].x + bh[p].x, hi + bi[p].y + bh[p].y);
        }
    }
}

// ---------------- K2: LSTM (regs weights, 2-CTA cluster/batch, fast act) ----------
__global__ void __launch_bounds__(256, 1) __cluster_dims__(2, 1, 1)
lstm_kernel(const float* __restrict__ w_hh) {
    __shared__ float Xs[Sn * 256];
    __shared__ __align__(16) float hbuf[2][HIDn];
    __shared__ float act[256];
    __shared__ __align__(8) u64 mbar[2];
    int tid = threadIdx.x;
    int b = blockIdx.x >> 1;
    unsigned rank = blockIdx.x & 1;
    unsigned peer = rank ^ 1;
    int q = tid >> 6, jj = tid & 63;
    int grow = q * 128 + (int)rank * 64 + jj;

    for (int t = 0; t < Sn; t++)
        Xs[t * 256 + tid] = sc_X[(b * Sn + t) * G4n + grow];
    if (tid < HIDn) hbuf[0][tid] = 0.f;
    unsigned mb0 = s2u(&mbar[0]);
    if (tid == 0) { mbar_init(mb0, 64); mbar_init(mb0 + 8, 64); }

    u64 w2r[64];
    const float4* wrow = (const float4*)(w_hh + (long)grow * HIDn);
#pragma unroll
    for (int k = 0; k < 32; k++) {
        float4 v = wrow[k];
        w2r[2 * k]     = pk2(v.x, v.y);
        w2r[2 * k + 1] = pk2(v.z, v.w);
    }
    __syncthreads();
    asm volatile("barrier.cluster.arrive.aligned;" ::: "memory");
    asm volatile("barrier.cluster.wait.aligned;" ::: "memory");

    unsigned peer_h  = mapa32(s2u(&hbuf[0][0]), peer);
    unsigned peer_mb = mapa32(mb0, peer);
    float c = 0.f;

    for (int t = 0; t < Sn; t++) {
        int cur = t & 1;
        if (t > 0) mbar_waitc(mb0 + cur * 8, ((unsigned)(t - 1) >> 1) & 1);
        const ulonglong2* hp = (const ulonglong2*)hbuf[cur];
        u64 a0 = 0ull, a1 = 0ull;
#pragma unroll
        for (int k = 0; k < 32; k++) {
            ulonglong2 hv = hp[k];
            fma2(a0, w2r[2 * k], hv.x);
            fma2(a1, w2r[2 * k + 1], hv.y);
        }
        float l0, h0, l1, h1;
        upk2(l0, h0, a0);
        upk2(l1, h1, a1);
        float g = Xs[t * 256 + tid] + ((l0 + h0) + (l1 + h1));
        act[tid] = (q == 2) ? tanh_fast(g) : sigm_fast(g);
        __syncthreads();
        if (tid < 64) {
            c = act[64 + tid] * c + act[tid] * act[128 + tid];
            float hh = act[192 + tid] * tanh_fast(c);
            int nxt = (t + 1) & 1;
            int hidx = (int)rank * 64 + tid;
            hbuf[nxt][hidx] = hh;
            sc_h[(b * Sn + t) * HIDn + hidx] = hh;
            if (t < Sn - 1) {
                st_remote_f32(peer_h + (unsigned)(nxt * HIDn + hidx) * 4u, hh);
                mbar_arrive_remote(peer_mb + (unsigned)nxt * 8u);
            }
        }
        __syncthreads();
    }
}

// ---------------- K3: combine, warp-per-position ----------------
__global__ void __launch_bounds__(256, 4)
combine_kernel(const int* __restrict__ word,
               const float* __restrict__ audio,
               const float* __restrict__ ph0t,
               const float* __restrict__ ph1t,
               const float* __restrict__ w_lin, const float* __restrict__ b_lin,
               const float* __restrict__ w1, const float* __restrict__ b1,
               const float* __restrict__ w2, const float* __restrict__ b2,
               const float* __restrict__ w3, const float* __restrict__ b3,
               const float* __restrict__ modw) {
    const unsigned FULL = 0xffffffffu;
    int lane = threadIdx.x & 31;
    int bs = blockIdx.x * 8 + (threadIdx.x >> 5);
    int o = lane & 15, half = lane >> 4;
    int w = word[bs];

    const float* hp = sc_h + bs * HIDn + half * 64;
    const float* wl = w_lin + o * HIDn + half * 64;
    float s = 0.f;
#pragma unroll
    for (int k = 0; k < 64; k += 4) {
        float4 hv = *(const float4*)&hp[k];
        float4 wv = *(const float4*)&wl[k];
        s = fmaf(hv.x, wv.x, s); s = fmaf(hv.y, wv.y, s);
        s = fmaf(hv.z, wv.z, s); s = fmaf(hv.w, wv.w, s);
    }
    s += __shfl_xor_sync(FULL, s, 16);
    float amp0 = s + b_lin[o];

    const float* ar = audio + bs * AUDn;
    const float* w1r = w1 + o * AUDn;
    float t = 0.f;
    int k0 = half * 37;
#pragma unroll
    for (int k = 0; k < 37; k++) t = fmaf(ar[k0 + k], w1r[k0 + k], t);
    t += __shfl_xor_sync(FULL, t, 16);
    float a1 = fmaxf(t + b1[o], 0.f);

    float s2 = b2[o];
#pragma unroll
    for (int k = 0; k < 16; k++)
        s2 = fmaf(__shfl_sync(FULL, a1, k), w2[o * 16 + k], s2);
    float a2 = fmaxf(s2, 0.f);

    float s3 = b3[o];
#pragma unroll
    for (int k = 0; k < 16; k++)
        s3 = fmaf(__shfl_sync(FULL, a2, k), w3[o * 16 + k], s3);
    float amp1 = fmaxf(s3, 0.f);

    float n0 = amp0 * amp0, n1 = amp1 * amp1;
#pragma unroll
    for (int sh = 8; sh; sh >>= 1) {
        n0 += __shfl_xor_sync(FULL, n0, sh);
        n1 += __shfl_xor_sync(FULL, n1, sh);
    }
    n0 = sqrtf(n0); n1 = sqrtf(n1);

    if (lane == 0) {
        float e0 = expf(modw[0]), e1 = expf(modw[1]);
        sc_weight[bs] = (e0 * n0 + e1 * n1) / (e0 + e1);
    }

    float an0 = amp0 / (n0 + 1e-10f);
    float p0 = ph0t[(long)w * D1n + o];
    float rr = an0 * cosf(p0), ii = an0 * sinf(p0);
    float tpr = rr - ii, tpi = rr + ii;
    float an1 = amp1 / (n1 + 1e-10f);
    float p1 = ph1t[(long)w * D2n + o];
    float r1l = an1 * cosf(p1), i1l = an1 * sinf(p1);

    float* dst = sc_RI + bs * 2 * DIMn + half * DIMn;
#pragma unroll
    for (int i = 0; i < 16; i++) {
        float tr = __shfl_sync(FULL, tpr, i);
        float ti = __shfl_sync(FULL, tpi, i);
        float v = half ? fmaf(tr, i1l, ti * r1l) : (tr * r1l - ti * i1l);
        dst[i * 16 + o] = v;
    }
}

// ---- K4: (1024x512) @ WT(512x256), K-split 4, conflict-free B columns ----
__global__ void __launch_bounds__(128, 4)
gemm_M() {
    __shared__ float As[32 * 128];   // 16 KB
    __shared__ float Bs[128 * 64];   // 32 KB
    int tid = threadIdx.x;
    int j0 = blockIdx.x * 64, bs0 = blockIdx.y * 32;
    int kbase = blockIdx.z * 128;
    int ct = tid & 15, rt = tid >> 4;
#pragma unroll
    for (int i = tid; i < 1024; i += 128) {
        int r = i >> 5, kq = i & 31;
        *(float4*)&As[r * 128 + kq * 4] =
            *(const float4*)&sc_RI[(bs0 + r) * 512 + kbase + kq * 4];
    }
#pragma unroll
    for (int i = tid; i < 2048; i += 128) {
        int r = i >> 4, cq = i & 15;
        *(float4*)&Bs[r * 64 + cq * 4] =
            *(const float4*)&sc_WT[(kbase + r) * 256 + j0 + cq * 4];
    }
    u64 acc[4][2];
#pragma unroll
    for (int q = 0; q < 4; q++) { acc[q][0] = 0ull; acc[q][1] = 0ull; }
    __syncthreads();
#pragma unroll 4
    for (int kk = 0; kk < 128; kk += 4) {
        float4 a0 = *(const float4*)&As[(rt * 4 + 0) * 128 + kk];
        float4 a1 = *(const float4*)&As[(rt * 4 + 1) * 128 + kk];
        float4 a2 = *(const float4*)&As[(rt * 4 + 2) * 128 + kk];
        float4 a3 = *(const float4*)&As[(rt * 4 + 3) * 128 + kk];
#define MDOT(T, E0, E1, E2, E3) { \
        u64 w0 = *(const u64*)&Bs[(kk + T) * 64 + 2 * ct]; \
        u64 w1 = *(const u64*)&Bs[(kk + T) * 64 + 32 + 2 * ct]; \
        u64 e; \
        e = pk2(E0, E0); fma2(acc[0][0], e, w0); fma2(acc[0][1], e, w1); \
        e = pk2(E1, E1); fma2(acc[1][0], e, w0); fma2(acc[1][1], e, w1); \
        e = pk2(E2, E2); fma2(acc[2][0], e, w0); fma2(acc[2][1], e, w1); \
        e = pk2(E3, E3); fma2(acc[3][0], e, w0); fma2(acc[3][1], e, w1); }
        MDOT(0, a0.x, a1.x, a2.x, a3.x)
        MDOT(1, a0.y, a1.y, a2.y, a3.y)
        MDOT(2, a0.z, a1.z, a2.z, a3.z)
        MDOT(3, a0.w, a1.w, a2.w, a3.w)
#undef MDOT
    }
    float* dstbuf = sc_PP4[blockIdx.z];
#pragma unroll
    for (int q = 0; q < 4; q++) {
        int row = bs0 + rt * 4 + q;
        float lo, hi;
        upk2(lo, hi, acc[q][0]);
        *(float2*)&dstbuf[row * 256 + j0 + 2 * ct] = make_float2(lo, hi);
        upk2(lo, hi, acc[q][1]);
        *(float2*)&dstbuf[row * 256 + j0 + 32 + 2 * ct] = make_float2(lo, hi);
    }
}

// ---------------- K5: windows + max-pool + final MLP ----------------
__global__ void pool_mlp(const float* __restrict__ fw1, const float* __restrict__ fb1,
                         const float* __restrict__ fw2, const float* __restrict__ fb2,
                         const float* __restrict__ fw3, const float* __restrict__ fb3,
                         float* __restrict__ out) {
    __shared__ float Msm[Sn * UNITSn];
    __shared__ float esm[Sn + 2];
    __shared__ float feat[UNITSn], y1[CELLn], y2[CELLn], red[2];
    int b = blockIdx.x;
    int u = threadIdx.x;
    for (int s = 0; s < Sn; s++) {
        int base = (b * Sn + s) * 256;
        float pr = (sc_PP4[0][base + u] + sc_PP4[1][base + u])
                 + (sc_PP4[2][base + u] + sc_PP4[3][base + u]);
        float pi = (sc_PP4[0][base + 128 + u] + sc_PP4[1][base + 128 + u])
                 + (sc_PP4[2][base + 128 + u] + sc_PP4[3][base + 128 + u]);
        Msm[s * UNITSn + u] = pr * pr + pi * pi;
    }
    if (u < Sn) esm[u] = expf(sc_weight[b * Sn + u]);
    if (u >= Sn && u < Sn + 2) esm[u] = 1.0f;
    __syncthreads();
    float f = 0.f;
    for (int s = 0; s < Sn; s++) {
        float m0 = Msm[s * UNITSn + u];
        float m1 = (s + 1 < Sn) ? Msm[(s + 1) * UNITSn + u] : 0.f;
        float m2 = (s + 2 < Sn) ? Msm[(s + 2) * UNITSn + u] : 0.f;
        float e0 = esm[s], e1 = esm[s + 1], e2 = esm[s + 2];
        float p3 = (e0 * m0 + e1 * m1 + e2 * m2) / (e0 + e1 + e2);
        f = fmaxf(f, fmaxf(m0, p3));
    }
    feat[u] = f;
    __syncthreads();
    if (u < CELLn) {
        float s = fb1[u];
        for (int k = 0; k < UNITSn; k++) s = fmaf(feat[k], fw1[u * UNITSn + k], s);
        y1[u] = fmaxf(s, 0.f);
    }
    __syncthreads();
    if (u < CELLn) {
        float s = fb2[u];
        for (int k = 0; k < CELLn; k++) s = fmaf(y1[k], fw2[u * CELLn + k], s);
        y2[u] = fmaxf(s, 0.f);
    }
    __syncthreads();
    if (u < CELLn) {
        float v = y2[u] * fw3[u];
        for (int o = 16; o > 0; o >>= 1) v += __shfl_down_sync(0xffffffffu, v, o);
        if ((u & 31) == 0) red[u >> 5] = v;
    }
    __syncthreads();
    if (u == 0) out[b] = red[0] + red[1] + fb3[0];
}

// ---------------- launch ----------------
extern "C" void kernel_launch(void* const* d_in, const int* in_sizes, int n_in,
                              void* d_out, int out_size) {
    const int*   word  = (const int*)  d_in[0];
    const float* audio = (const float*)d_in[1];
    const float* lut   = (const float*)d_in[2];
    const float* ph0   = (const float*)d_in[3];
    const float* ph1   = (const float*)d_in[4];
    const float* w_ih  = (const float*)d_in[5];
    const float* w_hh  = (const float*)d_in[6];
    const float* b_ih  = (const float*)d_in[7];
    const float* b_hh  = (const float*)d_in[8];
    const float* w_lin = (const float*)d_in[9];
    const float* b_lin = (const float*)d_in[10];
    const float* w1    = (const float*)d_in[11];
    const float* b1    = (const float*)d_in[12];
    const float* w2    = (const float*)d_in[13];
    const float* b2    = (const float*)d_in[14];
    const float* w3    = (const float*)d_in[15];
    const float* b3    = (const float*)d_in[16];
    const float* modw  = (const float*)d_in[17];
    const float* mr    = (const float*)d_in[18];
    const float* mi    = (const float*)d_in[19];
    const float* fw1   = (const float*)d_in[20];
    const float* fb1   = (const float*)d_in[21];
    const float* fw2   = (const float*)d_in[22];
    const float* fb2   = (const float*)d_in[23];
    const float* fw3   = (const float*)d_in[24];
    const float* fb3   = (const float*)d_in[25];
    float* out = (float*)d_out;

    cudaFuncSetAttribute(gemm_M, cudaFuncAttributePreferredSharedMemoryCarveout, 100);

    prep_WT<<<128, 256>>>(mr, mi);
    gemm_X<<<dim3(8, 16), 128>>>(word, lut, w_ih, b_ih, b_hh);
    lstm_kernel<<<64, 256>>>(w_hh);
    combine_kernel<<<128, 256>>>(word, audio, ph0, ph1, w_lin, b_lin,
                                 w1, b1, w2, b2, w3, b3, modw);
    gemm_M<<<dim3(4, 32, 4), 128>>>();
    pool_mlp<<<32, 128>>>(fw1, fb1, fw2, fb2, fw3, fb3, out);
}

// round 15
// speedup vs baseline: 1.1062x; 1.0062x over previous
#include <cuda_runtime.h>
#include <math.h>

#define Bn     32
#define Sn     32
#define BS     1024
#define EMBn   300
#define HIDn   128
#define G4n    512
#define AUDn   74
#define D1n    16
#define D2n    16
#define DIMn   256
#define UNITSn 128
#define CELLn  64

typedef unsigned long long u64;

// ---------------- scratch ----------------
__device__ __align__(16) float sc_X[BS * G4n];
__device__ __align__(16) float sc_h[BS * HIDn];
__device__ __align__(16) float sc_RI[BS * 2 * DIMn];
__device__ __align__(16) float sc_WT[2 * DIMn * 2 * UNITSn];  // 512 x 256
__device__ float sc_weight[BS];
__device__ __align__(16) float sc_PP4[4][BS * 2 * UNITSn];    // 4 K-split partials

// ---------------- f32x2 / ptx helpers ----------------
__device__ __forceinline__ u64 pk2(float x, float y) {
    u64 r; asm("mov.b64 %0,{%1,%2};" : "=l"(r) : "f"(x), "f"(y)); return r;
}
__device__ __forceinline__ void upk2(float& x, float& y, u64 v) {
    asm("mov.b64 {%0,%1},%2;" : "=f"(x), "=f"(y) : "l"(v));
}
__device__ __forceinline__ void fma2(u64& d, u64 a, u64 b) {
    asm("fma.rn.f32x2 %0,%1,%2,%0;" : "+l"(d) : "l"(a), "l"(b));
}
__device__ __forceinline__ float ex2f(float x) {
    float y; asm("ex2.approx.f32 %0,%1;" : "=f"(y) : "f"(x)); return y;
}
__device__ __forceinline__ float rcpf(float x) {
    float y; asm("rcp.approx.f32 %0,%1;" : "=f"(y) : "f"(x)); return y;
}
__device__ __forceinline__ float sigm_fast(float x) {
    return rcpf(1.0f + ex2f(-1.4426950408889634f * x));
}
__device__ __forceinline__ float tanh_fast(float x) {
    return 1.0f - 2.0f * rcpf(1.0f + ex2f(2.8853900817779268f * x));
}
__device__ __forceinline__ unsigned s2u(const void* p) {
    return (unsigned)__cvta_generic_to_shared(p);
}
__device__ __forceinline__ unsigned mapa32(unsigned a, unsigned r) {
    unsigned d; asm("mapa.shared::cluster.u32 %0,%1,%2;" : "=r"(d) : "r"(a), "r"(r));
    return d;
}
__device__ __forceinline__ void mbar_init(unsigned a, unsigned cnt) {
    asm volatile("mbarrier.init.shared.b64 [%0], %1;" :: "r"(a), "r"(cnt) : "memory");
}
__device__ __forceinline__ void mbar_arrive_remote(unsigned a) {
    asm volatile("mbarrier.arrive.release.cluster.shared::cluster.b64 _, [%0];"
                 :: "r"(a) : "memory");
}
__device__ __forceinline__ void st_remote_f32(unsigned a, float v) {
    asm volatile("st.shared::cluster.f32 [%0], %1;" :: "r"(a), "f"(v) : "memory");
}
__device__ __forceinline__ void mbar_waitc(unsigned a, unsigned parity) {
    asm volatile(
        "{\n\t.reg .pred P;\n"
        "WL%=:\n\t"
        "mbarrier.try_wait.parity.acquire.cluster.shared::cta.b64 P, [%0], %1;\n\t"
        "@P bra WD%=;\n\t"
        "bra WL%=;\n"
        "WD%=:\n\t}"
        :: "r"(a), "r"(parity) : "memory");
}

// ---------------- K1: X = emb[word] @ w_ih.T + b_ih + b_hh ----------------
__global__ void gemm_X(const int* __restrict__ word,
                       const float* __restrict__ lut,
                       const float* __restrict__ w_ih,
                       const float* __restrict__ b_ih,
                       const float* __restrict__ b_hh) {
    __shared__ float As[64 * 60];
    __shared__ float Bs[60 * 64];
    __shared__ int wd[64];
    int tid = threadIdx.x;
    int j0 = blockIdx.x * 64, bs0 = blockIdx.y * 64;
    int ct = tid & 7, rt = tid >> 3;
    if (tid < 64) wd[tid] = word[bs0 + tid];
    u64 acc[4][4];
#pragma unroll
    for (int q = 0; q < 4; q++)
#pragma unroll
        for (int p = 0; p < 4; p++) acc[q][p] = 0ull;
    int jb = j0 + ct * 8;
    float2 bi[4], bh[4];
#pragma unroll
    for (int p = 0; p < 4; p++) {
        bi[p] = *(const float2*)&b_ih[jb + 2 * p];
        bh[p] = *(const float2*)&b_hh[jb + 2 * p];
    }
    __syncthreads();
    for (int c = 0; c < 5; c++) {
        int kc = c * 60;
        for (int i = tid; i < 960; i += 128) {
            int r = i / 15, kq = i - r * 15;
            *(float4*)&As[r * 60 + kq * 4] =
                *(const float4*)&lut[(long)wd[r] * EMBn + kc + kq * 4];
        }
        for (int i = tid; i < 960; i += 128) {
            int j = i / 15, kq = i - j * 15;
            float4 v = *(const float4*)&w_ih[(long)(j0 + j) * EMBn + kc + kq * 4];
            int kb = kq * 4;
            Bs[(kb + 0) * 64 + j] = v.x;
            Bs[(kb + 1) * 64 + j] = v.y;
            Bs[(kb + 2) * 64 + j] = v.z;
            Bs[(kb + 3) * 64 + j] = v.w;
        }
        __syncthreads();
#pragma unroll 5
        for (int kk = 0; kk < 60; kk += 4) {
            float4 a0 = *(const float4*)&As[(rt * 4 + 0) * 60 + kk];
            float4 a1 = *(const float4*)&As[(rt * 4 + 1) * 60 + kk];
            float4 a2 = *(const float4*)&As[(rt * 4 + 2) * 60 + kk];
            float4 a3 = *(const float4*)&As[(rt * 4 + 3) * 60 + kk];
#define XDOT(T, E0, E1, E2, E3) { \
            const u64* bp = (const u64*)&Bs[(kk + T) * 64 + ct * 8]; \
            u64 w0 = bp[0], w1v = bp[1], w2v = bp[2], w3v = bp[3]; \
            u64 e; \
            e = pk2(E0, E0); fma2(acc[0][0], e, w0); fma2(acc[0][1], e, w1v); fma2(acc[0][2], e, w2v); fma2(acc[0][3], e, w3v); \
            e = pk2(E1, E1); fma2(acc[1][0], e, w0); fma2(acc[1][1], e, w1v); fma2(acc[1][2], e, w2v); fma2(acc[1][3], e, w3v); \
            e = pk2(E2, E2); fma2(acc[2][0], e, w0); fma2(acc[2][1], e, w1v); fma2(acc[2][2], e, w2v); fma2(acc[2][3], e, w3v); \
            e = pk2(E3, E3); fma2(acc[3][0], e, w0); fma2(acc[3][1], e, w1v); fma2(acc[3][2], e, w2v); fma2(acc[3][3], e, w3v); }
            XDOT(0, a0.x, a1.x, a2.x, a3.x)
            XDOT(1, a0.y, a1.y, a2.y, a3.y)
            XDOT(2, a0.z, a1.z, a2.z, a3.z)
            XDOT(3, a0.w, a1.w, a2.w, a3.w)
#undef XDOT
        }
        __syncthreads();
    }
#pragma unroll
    for (int q = 0; q < 4; q++) {
        int row = bs0 + rt * 4 + q;
#pragma unroll
        for (int p = 0; p < 4; p++) {
            float lo, hi; upk2(lo, hi, acc[q][p]);
            *(float2*)&sc_X[row * G4n + jb + 2 * p] =
                make_float2(lo + bi[p].x + bh[p].x, hi + bi[p].y + bh[p].y);
        }
    }
}

// ---------------- K2: LSTM (regs weights, 2-CTA cluster/batch, fast act) ----------
__global__ void __launch_bounds__(256, 1) __cluster_dims__(2, 1, 1)
lstm_kernel(const float* __restrict__ w_hh) {
    __shared__ float Xs[Sn * 256];
    __shared__ __align__(16) float hbuf[2][HIDn];
    __shared__ float act[256];
    __shared__ __align__(8) u64 mbar[2];
    int tid = threadIdx.x;
    int b = blockIdx.x >> 1;
    unsigned rank = blockIdx.x & 1;
    unsigned peer = rank ^ 1;
    int q = tid >> 6, jj = tid & 63;
    int grow = q * 128 + (int)rank * 64 + jj;

    for (int t = 0; t < Sn; t++)
        Xs[t * 256 + tid] = sc_X[(b * Sn + t) * G4n + grow];
    if (tid < HIDn) hbuf[0][tid] = 0.f;
    unsigned mb0 = s2u(&mbar[0]);
    if (tid == 0) { mbar_init(mb0, 64); mbar_init(mb0 + 8, 64); }

    u64 w2r[64];
    const float4* wrow = (const float4*)(w_hh + (long)grow * HIDn);
#pragma unroll
    for (int k = 0; k < 32; k++) {
        float4 v = wrow[k];
        w2r[2 * k]     = pk2(v.x, v.y);
        w2r[2 * k + 1] = pk2(v.z, v.w);
    }
    __syncthreads();
    asm volatile("barrier.cluster.arrive.aligned;" ::: "memory");
    asm volatile("barrier.cluster.wait.aligned;" ::: "memory");

    unsigned peer_h  = mapa32(s2u(&hbuf[0][0]), peer);
    unsigned peer_mb = mapa32(mb0, peer);
    float c = 0.f;

    for (int t = 0; t < Sn; t++) {
        int cur = t & 1;
        if (t > 0) mbar_waitc(mb0 + cur * 8, ((unsigned)(t - 1) >> 1) & 1);
        const ulonglong2* hp = (const ulonglong2*)hbuf[cur];
        u64 a0 = 0ull, a1 = 0ull;
#pragma unroll
        for (int k = 0; k < 32; k++) {
            ulonglong2 hv = hp[k];
            fma2(a0, w2r[2 * k], hv.x);
            fma2(a1, w2r[2 * k + 1], hv.y);
        }
        float l0, h0, l1, h1;
        upk2(l0, h0, a0);
        upk2(l1, h1, a1);
        float g = Xs[t * 256 + tid] + ((l0 + h0) + (l1 + h1));
        act[tid] = (q == 2) ? tanh_fast(g) : sigm_fast(g);
        __syncthreads();
        if (tid < 64) {
            c = act[64 + tid] * c + act[tid] * act[128 + tid];
            float hh = act[192 + tid] * tanh_fast(c);
            int nxt = (t + 1) & 1;
            int hidx = (int)rank * 64 + tid;
            hbuf[nxt][hidx] = hh;
            sc_h[(b * Sn + t) * HIDn + hidx] = hh;
            if (t < Sn - 1) {
                st_remote_f32(peer_h + (unsigned)(nxt * HIDn + hidx) * 4u, hh);
                mbar_arrive_remote(peer_mb + (unsigned)nxt * 8u);
            }
        }
        __syncthreads();
    }
}

// ---- K3: combine (blk 0..127, warp-per-position) | prep_WT (blk 128..255) ----
__global__ void __launch_bounds__(256)
combine_kernel(const int* __restrict__ word,
               const float* __restrict__ audio,
               const float* __restrict__ ph0t,
               const float* __restrict__ ph1t,
               const float* __restrict__ w_lin, const float* __restrict__ b_lin,
               const float* __restrict__ w1, const float* __restrict__ b1,
               const float* __restrict__ w2, const float* __restrict__ b2,
               const float* __restrict__ w3, const float* __restrict__ b3,
               const float* __restrict__ modw,
               const float* __restrict__ mr, const float* __restrict__ mi) {
    __shared__ float red[8];
    __shared__ float sinv;
    const unsigned FULL = 0xffffffffu;
    int tid = threadIdx.x;

    if (blockIdx.x >= 128) {
        // ---------- prep_WT for unit u ----------
        int u = blockIdx.x - 128;
        float r = mr[u * DIMn + tid], i = mi[u * DIMn + tid];
        float s = r * r + i * i;
        for (int sh = 16; sh; sh >>= 1) s += __shfl_down_sync(FULL, s, sh);
        if ((tid & 31) == 0) red[tid >> 5] = s;
        __syncthreads();
        if (tid == 0) {
            float t = 0.f;
            for (int k = 0; k < 8; k++) t += red[k];
            sinv = 1.0f / (sqrtf(t) + 1e-10f);
        }
        __syncthreads();
        float inv = sinv;
        sc_WT[tid * 256 + u]                   = r * inv;
        sc_WT[tid * 256 + UNITSn + u]          = -i * inv;
        sc_WT[(DIMn + tid) * 256 + u]          = i * inv;
        sc_WT[(DIMn + tid) * 256 + UNITSn + u] = r * inv;
        return;
    }

    // ---------- combine, warp-per-position ----------
    int lane = tid & 31;
    int bs = blockIdx.x * 8 + (tid >> 5);
    int o = lane & 15, half = lane >> 4;
    int w = word[bs];

    // earliest: dependent gathers (longest latency)
    float p0 = ph0t[(long)w * D1n + o];
    float p1 = ph1t[(long)w * D2n + o];

    // preload layer-2/3 weight rows into registers (parallel float4 loads)
    float4 w2q[4], w3q[4];
#pragma unroll
    for (int p = 0; p < 4; p++) {
        w2q[p] = *(const float4*)&w2[o * 16 + p * 4];
        w3q[p] = *(const float4*)&w3[o * 16 + p * 4];
    }
    float blv = b_lin[o], b1v = b1[o], b2v = b2[o], b3v = b3[o];

    // h-dot: 4 independent accumulator chains
    const float* hp = sc_h + bs * HIDn + half * 64;
    const float* wl = w_lin + o * HIDn + half * 64;
    float sx = 0.f, sy = 0.f, sz = 0.f, sw = 0.f;
#pragma unroll
    for (int k = 0; k < 64; k += 4) {
        float4 hv = *(const float4*)&hp[k];
        float4 wv = *(const float4*)&wl[k];
        sx = fmaf(hv.x, wv.x, sx); sy = fmaf(hv.y, wv.y, sy);
        sz = fmaf(hv.z, wv.z, sz); sw = fmaf(hv.w, wv.w, sw);
    }
    float s = (sx + sy) + (sz + sw);
    s += __shfl_xor_sync(FULL, s, 16);
    float amp0 = s + blv;

    // audio layer 1: 2 accumulator chains
    const float* ar = audio + bs * AUDn;
    const float* w1r = w1 + o * AUDn;
    int k0 = half * 37;
    float ta = 0.f, tb = 0.f;
#pragma unroll
    for (int k = 0; k < 36; k += 2) {
        ta = fmaf(ar[k0 + k], w1r[k0 + k], ta);
        tb = fmaf(ar[k0 + k + 1], w1r[k0 + k + 1], tb);
    }
    float t = ta + tb + ar[k0 + 36] * w1r[k0 + 36];
    t += __shfl_xor_sync(FULL, t, 16);
    float a1 = fmaxf(t + b1v, 0.f);

    // layer 2/3: register weights, shfl-fed
    float s2 = b2v;
#pragma unroll
    for (int p = 0; p < 4; p++) {
        s2 = fmaf(__shfl_sync(FULL, a1, 4 * p + 0), (p == 0 ? w2q[0].x : p == 1 ? w2q[1].x : p == 2 ? w2q[2].x : w2q[3].x), s2);
        s2 = fmaf(__shfl_sync(FULL, a1, 4 * p + 1), (p == 0 ? w2q[0].y : p == 1 ? w2q[1].y : p == 2 ? w2q[2].y : w2q[3].y), s2);
        s2 = fmaf(__shfl_sync(FULL, a1, 4 * p + 2), (p == 0 ? w2q[0].z : p == 1 ? w2q[1].z : p == 2 ? w2q[2].z : w2q[3].z), s2);
        s2 = fmaf(__shfl_sync(FULL, a1, 4 * p + 3), (p == 0 ? w2q[0].w : p == 1 ? w2q[1].w : p == 2 ? w2q[2].w : w2q[3].w), s2);
    }
    float a2 = fmaxf(s2, 0.f);

    float s3 = b3v;
#pragma unroll
    for (int p = 0; p < 4; p++) {
        s3 = fmaf(__shfl_sync(FULL, a2, 4 * p + 0), (p == 0 ? w3q[0].x : p == 1 ? w3q[1].x : p == 2 ? w3q[2].x : w3q[3].x), s3);
        s3 = fmaf(__shfl_sync(FULL, a2, 4 * p + 1), (p == 0 ? w3q[0].y : p == 1 ? w3q[1].y : p == 2 ? w3q[2].y : w3q[3].y), s3);
        s3 = fmaf(__shfl_sync(FULL, a2, 4 * p + 2), (p == 0 ? w3q[0].z : p == 1 ? w3q[1].z : p == 2 ? w3q[2].z : w3q[3].z), s3);
        s3 = fmaf(__shfl_sync(FULL, a2, 4 * p + 3), (p == 0 ? w3q[0].w : p == 1 ? w3q[1].w : p == 2 ? w3q[2].w : w3q[3].w), s3);
    }
    float amp1 = fmaxf(s3, 0.f);

    float n0 = amp0 * amp0, n1 = amp1 * amp1;
#pragma unroll
    for (int sh = 8; sh; sh >>= 1) {
        n0 += __shfl_xor_sync(FULL, n0, sh);
        n1 += __shfl_xor_sync(FULL, n1, sh);
    }
    n0 = sqrtf(n0); n1 = sqrtf(n1);

    if (lane == 0) {
        float e0 = expf(modw[0]), e1 = expf(modw[1]);
        sc_weight[bs] = (e0 * n0 + e1 * n1) / (e0 + e1);
    }

    float an0 = amp0 / (n0 + 1e-10f);
    float c0, s0;
    __sincosf(p0, &s0, &c0);
    float rr = an0 * c0, ii = an0 * s0;
    float tpr = rr - ii, tpi = rr + ii;
    float an1 = amp1 / (n1 + 1e-10f);
    float c1, s1;
    __sincosf(p1, &s1, &c1);
    float r1l = an1 * c1, i1l = an1 * s1;

    float* dst = sc_RI + bs * 2 * DIMn + half * DIMn;
#pragma unroll
    for (int i = 0; i < 16; i++) {
        float tr = __shfl_sync(FULL, tpr, i);
        float ti = __shfl_sync(FULL, tpi, i);
        float v = half ? fmaf(tr, i1l, ti * r1l) : (tr * r1l - ti * i1l);
        dst[i * 16 + o] = v;
    }
}

// ---- K4: (1024x512) @ WT(512x256), K-split 4, conflict-free B columns ----
__global__ void __launch_bounds__(128, 4)
gemm_M() {
    __shared__ float As[32 * 128];   // 16 KB
    __shared__ float Bs[128 * 64];   // 32 KB
    int tid = threadIdx.x;
    int j0 = blockIdx.x * 64, bs0 = blockIdx.y * 32;
    int kbase = blockIdx.z * 128;
    int ct = tid & 15, rt = tid >> 4;
#pragma unroll
    for (int i = tid; i < 1024; i += 128) {
        int r = i >> 5, kq = i & 31;
        *(float4*)&As[r * 128 + kq * 4] =
            *(const float4*)&sc_RI[(bs0 + r) * 512 + kbase + kq * 4];
    }
#pragma unroll
    for (int i = tid; i < 2048; i += 128) {
        int r = i >> 4, cq = i & 15;
        *(float4*)&Bs[r * 64 + cq * 4] =
            *(const float4*)&sc_WT[(kbase + r) * 256 + j0 + cq * 4];
    }
    u64 acc[4][2];
#pragma unroll
    for (int q = 0; q < 4; q++) { acc[q][0] = 0ull; acc[q][1] = 0ull; }
    __syncthreads();
#pragma unroll 4
    for (int kk = 0; kk < 128; kk += 4) {
        float4 a0 = *(const float4*)&As[(rt * 4 + 0) * 128 + kk];
        float4 a1 = *(const float4*)&As[(rt * 4 + 1) * 128 + kk];
        float4 a2 = *(const float4*)&As[(rt * 4 + 2) * 128 + kk];
        float4 a3 = *(const float4*)&As[(rt * 4 + 3) * 128 + kk];
#define MDOT(T, E0, E1, E2, E3) { \
        u64 w0 = *(const u64*)&Bs[(kk + T) * 64 + 2 * ct]; \
        u64 w1 = *(const u64*)&Bs[(kk + T) * 64 + 32 + 2 * ct]; \
        u64 e; \
        e = pk2(E0, E0); fma2(acc[0][0], e, w0); fma2(acc[0][1], e, w1); \
        e = pk2(E1, E1); fma2(acc[1][0], e, w0); fma2(acc[1][1], e, w1); \
        e = pk2(E2, E2); fma2(acc[2][0], e, w0); fma2(acc[2][1], e, w1); \
        e = pk2(E3, E3); fma2(acc[3][0], e, w0); fma2(acc[3][1], e, w1); }
        MDOT(0, a0.x, a1.x, a2.x, a3.x)
        MDOT(1, a0.y, a1.y, a2.y, a3.y)
        MDOT(2, a0.z, a1.z, a2.z, a3.z)
        MDOT(3, a0.w, a1.w, a2.w, a3.w)
#undef MDOT
    }
    float* dstbuf = sc_PP4[blockIdx.z];
#pragma unroll
    for (int q = 0; q < 4; q++) {
        int row = bs0 + rt * 4 + q;
        float lo, hi;
        upk2(lo, hi, acc[q][0]);
        *(float2*)&dstbuf[row * 256 + j0 + 2 * ct] = make_float2(lo, hi);
        upk2(lo, hi, acc[q][1]);
        *(float2*)&dstbuf[row * 256 + j0 + 32 + 2 * ct] = make_float2(lo, hi);
    }
}

// ---------------- K5: windows + max-pool + final MLP ----------------
__global__ void pool_mlp(const float* __restrict__ fw1, const float* __restrict__ fb1,
                         const float* __restrict__ fw2, const float* __restrict__ fb2,
                         const float* __restrict__ fw3, const float* __restrict__ fb3,
                         float* __restrict__ out) {
    __shared__ float Msm[Sn * UNITSn];
    __shared__ float esm[Sn + 2];
    __shared__ float feat[UNITSn], y1[CELLn], y2[CELLn], red[2];
    int b = blockIdx.x;
    int u = threadIdx.x;
    for (int s = 0; s < Sn; s++) {
        int base = (b * Sn + s) * 256;
        float pr = (sc_PP4[0][base + u] + sc_PP4[1][base + u])
                 + (sc_PP4[2][base + u] + sc_PP4[3][base + u]);
        float pi = (sc_PP4[0][base + 128 + u] + sc_PP4[1][base + 128 + u])
                 + (sc_PP4[2][base + 128 + u] + sc_PP4[3][base + 128 + u]);
        Msm[s * UNITSn + u] = pr * pr + pi * pi;
    }
    if (u < Sn) esm[u] = expf(sc_weight[b * Sn + u]);
    if (u >= Sn && u < Sn + 2) esm[u] = 1.0f;
    __syncthreads();
    float f = 0.f;
    for (int s = 0; s < Sn; s++) {
        float m0 = Msm[s * UNITSn + u];
        float m1 = (s + 1 < Sn) ? Msm[(s + 1) * UNITSn + u] : 0.f;
        float m2 = (s + 2 < Sn) ? Msm[(s + 2) * UNITSn + u] : 0.f;
        float e0 = esm[s], e1 = esm[s + 1], e2 = esm[s + 2];
        float p3 = (e0 * m0 + e1 * m1 + e2 * m2) / (e0 + e1 + e2);
        f = fmaxf(f, fmaxf(m0, p3));
    }
    feat[u] = f;
    __syncthreads();
    if (u < CELLn) {
        float s = fb1[u];
        for (int k = 0; k < UNITSn; k++) s = fmaf(feat[k], fw1[u * UNITSn + k], s);
        y1[u] = fmaxf(s, 0.f);
    }
    __syncthreads();
    if (u < CELLn) {
        float s = fb2[u];
        for (int k = 0; k < CELLn; k++) s = fmaf(y1[k], fw2[u * CELLn + k], s);
        y2[u] = fmaxf(s, 0.f);
    }
    __syncthreads();
    if (u < CELLn) {
        float v = y2[u] * fw3[u];
        for (int o = 16; o > 0; o >>= 1) v += __shfl_down_sync(0xffffffffu, v, o);
        if ((u & 31) == 0) red[u >> 5] = v;
    }
    __syncthreads();
    if (u == 0) out[b] = red[0] + red[1] + fb3[0];
}

// ---------------- launch ----------------
extern "C" void kernel_launch(void* const* d_in, const int* in_sizes, int n_in,
                              void* d_out, int out_size) {
    const int*   word  = (const int*)  d_in[0];
    const float* audio = (const float*)d_in[1];
    const float* lut   = (const float*)d_in[2];
    const float* ph0   = (const float*)d_in[3];
    const float* ph1   = (const float*)d_in[4];
    const float* w_ih  = (const float*)d_in[5];
    const float* w_hh  = (const float*)d_in[6];
    const float* b_ih  = (const float*)d_in[7];
    const float* b_hh  = (const float*)d_in[8];
    const float* w_lin = (const float*)d_in[9];
    const float* b_lin = (const float*)d_in[10];
    const float* w1    = (const float*)d_in[11];
    const float* b1    = (const float*)d_in[12];
    const float* w2    = (const float*)d_in[13];
    const float* b2    = (const float*)d_in[14];
    const float* w3    = (const float*)d_in[15];
    const float* b3    = (const float*)d_in[16];
    const float* modw  = (const float*)d_in[17];
    const float* mr    = (const float*)d_in[18];
    const float* mi    = (const float*)d_in[19];
    const float* fw1   = (const float*)d_in[20];
    const float* fb1   = (const float*)d_in[21];
    const float* fw2   = (const float*)d_in[22];
    const float* fb2   = (const float*)d_in[23];
    const float* fw3   = (const float*)d_in[24];
    const float* fb3   = (const float*)d_in[25];
    float* out = (float*)d_out;

    cudaFuncSetAttribute(gemm_M, cudaFuncAttributePreferredSharedMemoryCarveout, 100);

    gemm_X<<<dim3(8, 16), 128>>>(word, lut, w_ih, b_ih, b_hh);
    lstm_kernel<<<64, 256>>>(w_hh);
    combine_kernel<<<256, 256>>>(word, audio, ph0, ph1, w_lin, b_lin,
                                 w1, b1, w2, b2, w3, b3, modw, mr, mi);
    gemm_M<<<dim3(4, 32, 4), 128>>>();
    pool_mlp<<<32, 128>>>(fw1, fb1, fw2, fb2, fw3, fb3, out);
}

// round 16
// speedup vs baseline: 1.2511x; 1.1310x over previous
#include <cuda_runtime.h>
#include <math.h>

#define Bn     32
#define Sn     32
#define BS     1024
#define EMBn   300
#define HIDn   128
#define G4n    512
#define AUDn   74
#define D1n    16
#define D2n    16
#define DIMn   256
#define UNITSn 128
#define CELLn  64

typedef unsigned long long u64;

// ---------------- scratch ----------------
__device__ __align__(16) float sc_X[BS * G4n];
__device__ __align__(16) float sc_h[BS * HIDn];
__device__ __align__(16) float sc_RI[BS * 2 * DIMn];
__device__ __align__(16) float sc_WT[2 * DIMn * 2 * UNITSn];  // 512 x 256
__device__ float sc_weight[BS];
__device__ __align__(16) float sc_PP4[4][BS * 2 * UNITSn];    // 4 K-split partials

// ---------------- f32x2 / ptx helpers ----------------
__device__ __forceinline__ u64 pk2(float x, float y) {
    u64 r; asm("mov.b64 %0,{%1,%2};" : "=l"(r) : "f"(x), "f"(y)); return r;
}
__device__ __forceinline__ void upk2(float& x, float& y, u64 v) {
    asm("mov.b64 {%0,%1},%2;" : "=f"(x), "=f"(y) : "l"(v));
}
__device__ __forceinline__ void fma2(u64& d, u64 a, u64 b) {
    asm("fma.rn.f32x2 %0,%1,%2,%0;" : "+l"(d) : "l"(a), "l"(b));
}
__device__ __forceinline__ float ex2f(float x) {
    float y; asm("ex2.approx.f32 %0,%1;" : "=f"(y) : "f"(x)); return y;
}
__device__ __forceinline__ float rcpf(float x) {
    float y; asm("rcp.approx.f32 %0,%1;" : "=f"(y) : "f"(x)); return y;
}
__device__ __forceinline__ float sigm_fast(float x) {
    return rcpf(1.0f + ex2f(-1.4426950408889634f * x));
}
__device__ __forceinline__ float tanh_fast(float x) {
    return 1.0f - 2.0f * rcpf(1.0f + ex2f(2.8853900817779268f * x));
}
__device__ __forceinline__ unsigned s2u(const void* p) {
    return (unsigned)__cvta_generic_to_shared(p);
}
__device__ __forceinline__ unsigned mapa32(unsigned a, unsigned r) {
    unsigned d; asm("mapa.shared::cluster.u32 %0,%1,%2;" : "=r"(d) : "r"(a), "r"(r));
    return d;
}
__device__ __forceinline__ void mbar_init(unsigned a, unsigned cnt) {
    asm volatile("mbarrier.init.shared.b64 [%0], %1;" :: "r"(a), "r"(cnt) : "memory");
}
__device__ __forceinline__ void mbar_arm_tx(unsigned a, unsigned bytes) {
    asm volatile("mbarrier.arrive.expect_tx.shared::cta.b64 _, [%0], %1;"
                 :: "r"(a), "r"(bytes) : "memory");
}
__device__ __forceinline__ void st_async_remote(unsigned addr, float v, unsigned mbar) {
    asm volatile("st.async.shared::cluster.mbarrier::complete_tx::bytes.b32 [%0], %1, [%2];"
                 :: "r"(addr), "r"(__float_as_uint(v)), "r"(mbar) : "memory");
}
__device__ __forceinline__ void mbar_waitc(unsigned a, unsigned parity) {
    asm volatile(
        "{\n\t.reg .pred P;\n"
        "WL%=:\n\t"
        "mbarrier.try_wait.parity.acquire.cluster.shared::cta.b64 P, [%0], %1;\n\t"
        "@P bra WD%=;\n\t"
        "bra WL%=;\n"
        "WD%=:\n\t}"
        :: "r"(a), "r"(parity) : "memory");
}

// ---------------- K1: X = emb[word] @ w_ih.T + b_ih + b_hh ----------------
__global__ void gemm_X(const int* __restrict__ word,
                       const float* __restrict__ lut,
                       const float* __restrict__ w_ih,
                       const float* __restrict__ b_ih,
                       const float* __restrict__ b_hh) {
    __shared__ float As[64 * 60];
    __shared__ float Bs[60 * 64];
    __shared__ int wd[64];
    int tid = threadIdx.x;
    int j0 = blockIdx.x * 64, bs0 = blockIdx.y * 64;
    int ct = tid & 7, rt = tid >> 3;
    if (tid < 64) wd[tid] = word[bs0 + tid];
    u64 acc[4][4];
#pragma unroll
    for (int q = 0; q < 4; q++)
#pragma unroll
        for (int p = 0; p < 4; p++) acc[q][p] = 0ull;
    int jb = j0 + ct * 8;
    float2 bi[4], bh[4];
#pragma unroll
    for (int p = 0; p < 4; p++) {
        bi[p] = *(const float2*)&b_ih[jb + 2 * p];
        bh[p] = *(const float2*)&b_hh[jb + 2 * p];
    }
    __syncthreads();
    for (int c = 0; c < 5; c++) {
        int kc = c * 60;
        for (int i = tid; i < 960; i += 128) {
            int r = i / 15, kq = i - r * 15;
            *(float4*)&As[r * 60 + kq * 4] =
                *(const float4*)&lut[(long)wd[r] * EMBn + kc + kq * 4];
        }
        for (int i = tid; i < 960; i += 128) {
            int j = i / 15, kq = i - j * 15;
            float4 v = *(const float4*)&w_ih[(long)(j0 + j) * EMBn + kc + kq * 4];
            int kb = kq * 4;
            Bs[(kb + 0) * 64 + j] = v.x;
            Bs[(kb + 1) * 64 + j] = v.y;
            Bs[(kb + 2) * 64 + j] = v.z;
            Bs[(kb + 3) * 64 + j] = v.w;
        }
        __syncthreads();
#pragma unroll 5
        for (int kk = 0; kk < 60; kk += 4) {
            float4 a0 = *(const float4*)&As[(rt * 4 + 0) * 60 + kk];
            float4 a1 = *(const float4*)&As[(rt * 4 + 1) * 60 + kk];
            float4 a2 = *(const float4*)&As[(rt * 4 + 2) * 60 + kk];
            float4 a3 = *(const float4*)&As[(rt * 4 + 3) * 60 + kk];
#define XDOT(T, E0, E1, E2, E3) { \
            const u64* bp = (const u64*)&Bs[(kk + T) * 64 + ct * 8]; \
            u64 w0 = bp[0], w1v = bp[1], w2v = bp[2], w3v = bp[3]; \
            u64 e; \
            e = pk2(E0, E0); fma2(acc[0][0], e, w0); fma2(acc[0][1], e, w1v); fma2(acc[0][2], e, w2v); fma2(acc[0][3], e, w3v); \
            e = pk2(E1, E1); fma2(acc[1][0], e, w0); fma2(acc[1][1], e, w1v); fma2(acc[1][2], e, w2v); fma2(acc[1][3], e, w3v); \
            e = pk2(E2, E2); fma2(acc[2][0], e, w0); fma2(acc[2][1], e, w1v); fma2(acc[2][2], e, w2v); fma2(acc[2][3], e, w3v); \
            e = pk2(E3, E3); fma2(acc[3][0], e, w0); fma2(acc[3][1], e, w1v); fma2(acc[3][2], e, w2v); fma2(acc[3][3], e, w3v); }
            XDOT(0, a0.x, a1.x, a2.x, a3.x)
            XDOT(1, a0.y, a1.y, a2.y, a3.y)
            XDOT(2, a0.z, a1.z, a2.z, a3.z)
            XDOT(3, a0.w, a1.w, a2.w, a3.w)
#undef XDOT
        }
        __syncthreads();
    }
#pragma unroll
    for (int q = 0; q < 4; q++) {
        int row = bs0 + rt * 4 + q;
#pragma unroll
        for (int p = 0; p < 4; p++) {
            float lo, hi; upk2(lo, hi, acc[q][p]);
            *(float2*)&sc_X[row * G4n + jb + 2 * p] =
                make_float2(lo + bi[p].x + bh[p].x, hi + bi[p].y + bh[p].y);
        }
    }
}

// ---- K2: LSTM (regs weights, 2-CTA cluster/batch, st.async h-handoff) ----
__global__ void __launch_bounds__(256, 1) __cluster_dims__(2, 1, 1)
lstm_kernel(const float* __restrict__ w_hh) {
    __shared__ float Xs[Sn * 256];
    __shared__ __align__(16) float hbuf[2][HIDn];
    __shared__ float act[256];
    __shared__ __align__(8) u64 mbar[2];
    int tid = threadIdx.x;
    int b = blockIdx.x >> 1;
    unsigned rank = blockIdx.x & 1;
    unsigned peer = rank ^ 1;
    int q = tid >> 6, jj = tid & 63;
    int grow = q * 128 + (int)rank * 64 + jj;

    for (int t = 0; t < Sn; t++)
        Xs[t * 256 + tid] = sc_X[(b * Sn + t) * G4n + grow];
    if (tid < HIDn) hbuf[0][tid] = 0.f;
    unsigned mb0 = s2u(&mbar[0]);
    if (tid == 0) { mbar_init(mb0, 1); mbar_init(mb0 + 8, 1); }

    u64 w2r[64];
    const float4* wrow = (const float4*)(w_hh + (long)grow * HIDn);
#pragma unroll
    for (int k = 0; k < 32; k++) {
        float4 v = wrow[k];
        w2r[2 * k]     = pk2(v.x, v.y);
        w2r[2 * k + 1] = pk2(v.z, v.w);
    }
    __syncthreads();
    asm volatile("barrier.cluster.arrive.aligned;" ::: "memory");
    asm volatile("barrier.cluster.wait.aligned;" ::: "memory");

    unsigned peer_h  = mapa32(s2u(&hbuf[0][0]), peer);
    unsigned peer_mb = mapa32(mb0, peer);
    float c = 0.f;

    for (int t = 0; t < Sn; t++) {
        int cur = t & 1;
        int nxt = cur ^ 1;
        if (t > 0) mbar_waitc(mb0 + cur * 8, ((unsigned)(t - 1) >> 1) & 1);
        // arm slot nxt to receive peer's 64 floats of h[t] (256 tx bytes)
        if (tid == 0 && t < Sn - 1)
            mbar_arm_tx(mb0 + (unsigned)nxt * 8u, 256u);
        const ulonglong2* hp = (const ulonglong2*)hbuf[cur];
        u64 a0 = 0ull, a1 = 0ull;
#pragma unroll
        for (int k = 0; k < 32; k++) {
            ulonglong2 hv = hp[k];
            fma2(a0, w2r[2 * k], hv.x);
            fma2(a1, w2r[2 * k + 1], hv.y);
        }
        float l0, h0, l1, h1;
        upk2(l0, h0, a0);
        upk2(l1, h1, a1);
        float g = Xs[t * 256 + tid] + ((l0 + h0) + (l1 + h1));
        act[tid] = (q == 2) ? tanh_fast(g) : sigm_fast(g);
        __syncthreads();
        if (tid < 64) {
            c = act[64 + tid] * c + act[tid] * act[128 + tid];
            float hh = act[192 + tid] * tanh_fast(c);
            int hidx = (int)rank * 64 + tid;
            hbuf[nxt][hidx] = hh;
            sc_h[(b * Sn + t) * HIDn + hidx] = hh;
            if (t < Sn - 1)
                st_async_remote(peer_h + (unsigned)(nxt * HIDn + hidx) * 4u, hh,
                                peer_mb + (unsigned)nxt * 8u);
        }
        __syncthreads();
    }
}

// ---- K3: combine (blk 0..127, warp-per-position) | prep_WT (blk 128..255) ----
__global__ void __launch_bounds__(256)
combine_kernel(const int* __restrict__ word,
               const float* __restrict__ audio,
               const float* __restrict__ ph0t,
               const float* __restrict__ ph1t,
               const float* __restrict__ w_lin, const float* __restrict__ b_lin,
               const float* __restrict__ w1, const float* __restrict__ b1,
               const float* __restrict__ w2, const float* __restrict__ b2,
               const float* __restrict__ w3, const float* __restrict__ b3,
               const float* __restrict__ modw,
               const float* __restrict__ mr, const float* __restrict__ mi) {
    __shared__ float red[8];
    __shared__ float sinv;
    const unsigned FULL = 0xffffffffu;
    int tid = threadIdx.x;

    if (blockIdx.x >= 128) {
        int u = blockIdx.x - 128;
        float r = mr[u * DIMn + tid], i = mi[u * DIMn + tid];
        float s = r * r + i * i;
        for (int sh = 16; sh; sh >>= 1) s += __shfl_down_sync(FULL, s, sh);
        if ((tid & 31) == 0) red[tid >> 5] = s;
        __syncthreads();
        if (tid == 0) {
            float t = 0.f;
            for (int k = 0; k < 8; k++) t += red[k];
            sinv = 1.0f / (sqrtf(t) + 1e-10f);
        }
        __syncthreads();
        float inv = sinv;
        sc_WT[tid * 256 + u]                   = r * inv;
        sc_WT[tid * 256 + UNITSn + u]          = -i * inv;
        sc_WT[(DIMn + tid) * 256 + u]          = i * inv;
        sc_WT[(DIMn + tid) * 256 + UNITSn + u] = r * inv;
        return;
    }

    int lane = tid & 31;
    int bs = blockIdx.x * 8 + (tid >> 5);
    int o = lane & 15, half = lane >> 4;
    int w = word[bs];

    float p0 = ph0t[(long)w * D1n + o];
    float p1 = ph1t[(long)w * D2n + o];

    float4 w2q[4], w3q[4];
#pragma unroll
    for (int p = 0; p < 4; p++) {
        w2q[p] = *(const float4*)&w2[o * 16 + p * 4];
        w3q[p] = *(const float4*)&w3[o * 16 + p * 4];
    }
    float blv = b_lin[o], b1v = b1[o], b2v = b2[o], b3v = b3[o];

    const float* hp = sc_h + bs * HIDn + half * 64;
    const float* wl = w_lin + o * HIDn + half * 64;
    float sx = 0.f, sy = 0.f, sz = 0.f, sw = 0.f;
#pragma unroll
    for (int k = 0; k < 64; k += 4) {
        float4 hv = *(const float4*)&hp[k];
        float4 wv = *(const float4*)&wl[k];
        sx = fmaf(hv.x, wv.x, sx); sy = fmaf(hv.y, wv.y, sy);
        sz = fmaf(hv.z, wv.z, sz); sw = fmaf(hv.w, wv.w, sw);
    }
    float s = (sx + sy) + (sz + sw);
    s += __shfl_xor_sync(FULL, s, 16);
    float amp0 = s + blv;

    const float* ar = audio + bs * AUDn;
    const float* w1r = w1 + o * AUDn;
    int k0 = half * 37;
    float ta = 0.f, tb = 0.f;
#pragma unroll
    for (int k = 0; k < 36; k += 2) {
        ta = fmaf(ar[k0 + k], w1r[k0 + k], ta);
        tb = fmaf(ar[k0 + k + 1], w1r[k0 + k + 1], tb);
    }
    float t = ta + tb + ar[k0 + 36] * w1r[k0 + 36];
    t += __shfl_xor_sync(FULL, t, 16);
    float a1 = fmaxf(t + b1v, 0.f);

    float s2 = b2v;
#pragma unroll
    for (int p = 0; p < 4; p++) {
        s2 = fmaf(__shfl_sync(FULL, a1, 4 * p + 0), (p == 0 ? w2q[0].x : p == 1 ? w2q[1].x : p == 2 ? w2q[2].x : w2q[3].x), s2);
        s2 = fmaf(__shfl_sync(FULL, a1, 4 * p + 1), (p == 0 ? w2q[0].y : p == 1 ? w2q[1].y : p == 2 ? w2q[2].y : w2q[3].y), s2);
        s2 = fmaf(__shfl_sync(FULL, a1, 4 * p + 2), (p == 0 ? w2q[0].z : p == 1 ? w2q[1].z : p == 2 ? w2q[2].z : w2q[3].z), s2);
        s2 = fmaf(__shfl_sync(FULL, a1, 4 * p + 3), (p == 0 ? w2q[0].w : p == 1 ? w2q[1].w : p == 2 ? w2q[2].w : w2q[3].w), s2);
    }
    float a2 = fmaxf(s2, 0.f);

    float s3 = b3v;
#pragma unroll
    for (int p = 0; p < 4; p++) {
        s3 = fmaf(__shfl_sync(FULL, a2, 4 * p + 0), (p == 0 ? w3q[0].x : p == 1 ? w3q[1].x : p == 2 ? w3q[2].x : w3q[3].x), s3);
        s3 = fmaf(__shfl_sync(FULL, a2, 4 * p + 1), (p == 0 ? w3q[0].y : p == 1 ? w3q[1].y : p == 2 ? w3q[2].y : w3q[3].y), s3);
        s3 = fmaf(__shfl_sync(FULL, a2, 4 * p + 2), (p == 0 ? w3q[0].z : p == 1 ? w3q[1].z : p == 2 ? w3q[2].z : w3q[3].z), s3);
        s3 = fmaf(__shfl_sync(FULL, a2, 4 * p + 3), (p == 0 ? w3q[0].w : p == 1 ? w3q[1].w : p == 2 ? w3q[2].w : w3q[3].w), s3);
    }
    float amp1 = fmaxf(s3, 0.f);

    float n0 = amp0 * amp0, n1 = amp1 * amp1;
#pragma unroll
    for (int sh = 8; sh; sh >>= 1) {
        n0 += __shfl_xor_sync(FULL, n0, sh);
        n1 += __shfl_xor_sync(FULL, n1, sh);
    }
    n0 = sqrtf(n0); n1 = sqrtf(n1);

    if (lane == 0) {
        float e0 = expf(modw[0]), e1 = expf(modw[1]);
        sc_weight[bs] = (e0 * n0 + e1 * n1) / (e0 + e1);
    }

    float an0 = amp0 / (n0 + 1e-10f);
    float c0, s0;
    __sincosf(p0, &s0, &c0);
    float rr = an0 * c0, ii = an0 * s0;
    float tpr = rr - ii, tpi = rr + ii;
    float an1 = amp1 / (n1 + 1e-10f);
    float c1, s1;
    __sincosf(p1, &s1, &c1);
    float r1l = an1 * c1, i1l = an1 * s1;

    float* dst = sc_RI + bs * 2 * DIMn + half * DIMn;
#pragma unroll
    for (int i = 0; i < 16; i++) {
        float tr = __shfl_sync(FULL, tpr, i);
        float ti = __shfl_sync(FULL, tpi, i);
        float v = half ? fmaf(tr, i1l, ti * r1l) : (tr * r1l - ti * i1l);
        dst[i * 16 + o] = v;
    }
}

// ---- K4: (1024x512) @ WT(512x256), K-split 4, conflict-free B columns ----
__global__ void __launch_bounds__(128, 4)
gemm_M() {
    __shared__ float As[32 * 128];   // 16 KB
    __shared__ float Bs[128 * 64];   // 32 KB
    int tid = threadIdx.x;
    int j0 = blockIdx.x * 64, bs0 = blockIdx.y * 32;
    int kbase = blockIdx.z * 128;
    int ct = tid & 15, rt = tid >> 4;
#pragma unroll
    for (int i = tid; i < 1024; i += 128) {
        int r = i >> 5, kq = i & 31;
        *(float4*)&As[r * 128 + kq * 4] =
            *(const float4*)&sc_RI[(bs0 + r) * 512 + kbase + kq * 4];
    }
#pragma unroll
    for (int i = tid; i < 2048; i += 128) {
        int r = i >> 4, cq = i & 15;
        *(float4*)&Bs[r * 64 + cq * 4] =
            *(const float4*)&sc_WT[(kbase + r) * 256 + j0 + cq * 4];
    }
    u64 acc[4][2];
#pragma unroll
    for (int q = 0; q < 4; q++) { acc[q][0] = 0ull; acc[q][1] = 0ull; }
    __syncthreads();
#pragma unroll 4
    for (int kk = 0; kk < 128; kk += 4) {
        float4 a0 = *(const float4*)&As[(rt * 4 + 0) * 128 + kk];
        float4 a1 = *(const float4*)&As[(rt * 4 + 1) * 128 + kk];
        float4 a2 = *(const float4*)&As[(rt * 4 + 2) * 128 + kk];
        float4 a3 = *(const float4*)&As[(rt * 4 + 3) * 128 + kk];
#define MDOT(T, E0, E1, E2, E3) { \
        u64 w0 = *(const u64*)&Bs[(kk + T) * 64 + 2 * ct]; \
        u64 w1 = *(const u64*)&Bs[(kk + T) * 64 + 32 + 2 * ct]; \
        u64 e; \
        e = pk2(E0, E0); fma2(acc[0][0], e, w0); fma2(acc[0][1], e, w1); \
        e = pk2(E1, E1); fma2(acc[1][0], e, w0); fma2(acc[1][1], e, w1); \
        e = pk2(E2, E2); fma2(acc[2][0], e, w0); fma2(acc[2][1], e, w1); \
        e = pk2(E3, E3); fma2(acc[3][0], e, w0); fma2(acc[3][1], e, w1); }
        MDOT(0, a0.x, a1.x, a2.x, a3.x)
        MDOT(1, a0.y, a1.y, a2.y, a3.y)
        MDOT(2, a0.z, a1.z, a2.z, a3.z)
        MDOT(3, a0.w, a1.w, a2.w, a3.w)
#undef MDOT
    }
    float* dstbuf = sc_PP4[blockIdx.z];
#pragma unroll
    for (int q = 0; q < 4; q++) {
        int row = bs0 + rt * 4 + q;
        float lo, hi;
        upk2(lo, hi, acc[q][0]);
        *(float2*)&dstbuf[row * 256 + j0 + 2 * ct] = make_float2(lo, hi);
        upk2(lo, hi, acc[q][1]);
        *(float2*)&dstbuf[row * 256 + j0 + 32 + 2 * ct] = make_float2(lo, hi);
    }
}

// ---------------- K5: windows + max-pool + final MLP ----------------
__global__ void pool_mlp(const float* __restrict__ fw1, const float* __restrict__ fb1,
                         const float* __restrict__ fw2, const float* __restrict__ fb2,
                         const float* __restrict__ fw3, const float* __restrict__ fb3,
                         float* __restrict__ out) {
    __shared__ float Msm[Sn * UNITSn];
    __shared__ float esm[Sn + 2];
    __shared__ float feat[UNITSn], y1[CELLn], y2[CELLn], red[2];
    int b = blockIdx.x;
    int u = threadIdx.x;
    for (int s = 0; s < Sn; s++) {
        int base = (b * Sn + s) * 256;
        float pr = (sc_PP4[0][base + u] + sc_PP4[1][base + u])
                 + (sc_PP4[2][base + u] + sc_PP4[3][base + u]);
        float pi = (sc_PP4[0][base + 128 + u] + sc_PP4[1][base + 128 + u])
                 + (sc_PP4[2][base + 128 + u] + sc_PP4[3][base + 128 + u]);
        Msm[s * UNITSn + u] = pr * pr + pi * pi;
    }
    if (u < Sn) esm[u] = expf(sc_weight[b * Sn + u]);
    if (u >= Sn && u < Sn + 2) esm[u] = 1.0f;
    __syncthreads();
    float f = 0.f;
    for (int s = 0; s < Sn; s++) {
        float m0 = Msm[s * UNITSn + u];
        float m1 = (s + 1 < Sn) ? Msm[(s + 1) * UNITSn + u] : 0.f;
        float m2 = (s + 2 < Sn) ? Msm[(s + 2) * UNITSn + u] : 0.f;
        float e0 = esm[s], e1 = esm[s + 1], e2 = esm[s + 2];
        float p3 = (e0 * m0 + e1 * m1 + e2 * m2) / (e0 + e1 + e2);
        f = fmaxf(f, fmaxf(m0, p3));
    }
    feat[u] = f;
    __syncthreads();
    if (u < CELLn) {
        float s = fb1[u];
        for (int k = 0; k < UNITSn; k++) s = fmaf(feat[k], fw1[u * UNITSn + k], s);
        y1[u] = fmaxf(s, 0.f);
    }
    __syncthreads();
    if (u < CELLn) {
        float s = fb2[u];
        for (int k = 0; k < CELLn; k++) s = fmaf(y1[k], fw2[u * CELLn + k], s);
        y2[u] = fmaxf(s, 0.f);
    }
    __syncthreads();
    if (u < CELLn) {
        float v = y2[u] * fw3[u];
        for (int o = 16; o > 0; o >>= 1) v += __shfl_down_sync(0xffffffffu, v, o);
        if ((u & 31) == 0) red[u >> 5] = v;
    }
    __syncthreads();
    if (u == 0) out[b] = red[0] + red[1] + fb3[0];
}

// ---------------- launch ----------------
extern "C" void kernel_launch(void* const* d_in, const int* in_sizes, int n_in,
                              void* d_out, int out_size) {
    const int*   word  = (const int*)  d_in[0];
    const float* audio = (const float*)d_in[1];
    const float* lut   = (const float*)d_in[2];
    const float* ph0   = (const float*)d_in[3];
    const float* ph1   = (const float*)d_in[4];
    const float* w_ih  = (const float*)d_in[5];
    const float* w_hh  = (const float*)d_in[6];
    const float* b_ih  = (const float*)d_in[7];
    const float* b_hh  = (const float*)d_in[8];
    const float* w_lin = (const float*)d_in[9];
    const float* b_lin = (const float*)d_in[10];
    const float* w1    = (const float*)d_in[11];
    const float* b1    = (const float*)d_in[12];
    const float* w2    = (const float*)d_in[13];
    const float* b2    = (const float*)d_in[14];
    const float* w3    = (const float*)d_in[15];
    const float* b3    = (const float*)d_in[16];
    const float* modw  = (const float*)d_in[17];
    const float* mr    = (const float*)d_in[18];
    const float* mi    = (const float*)d_in[19];
    const float* fw1   = (const float*)d_in[20];
    const float* fb1   = (const float*)d_in[21];
    const float* fw2   = (const float*)d_in[22];
    const float* fb2   = (const float*)d_in[23];
    const float* fw3   = (const float*)d_in[24];
    const float* fb3   = (const float*)d_in[25];
    float* out = (float*)d_out;

    cudaFuncSetAttribute(gemm_M, cudaFuncAttributePreferredSharedMemoryCarveout, 100);

    gemm_X<<<dim3(8, 16), 128>>>(word, lut, w_ih, b_ih, b_hh);
    lstm_kernel<<<64, 256>>>(w_hh);
    combine_kernel<<<256, 256>>>(word, audio, ph0, ph1, w_lin, b_lin,
                                 w1, b1, w2, b2, w3, b3, modw, mr, mi);
    gemm_M<<<dim3(4, 32, 4), 128>>>();
    pool_mlp<<<32, 128>>>(fw1, fb1, fw2, fb2, fw3, fb3, out);
}